// round 15
// baseline (speedup 1.0000x reference)
#include <cuda_runtime.h>
#include <cuda_bf16.h>
#include <math.h>
#include <stdint.h>

#define NTOK 4096
#define NE   8
#define HD   1024
#define FD   4096
#define CAP  2048

// ---------------- scratch (device globals) ----------------
__device__ float g_h[(size_t)NE * CAP * FD];     // 256 MB intermediate gelu(up)
__device__ int   g_tok[NE * NTOK];
__device__ float g_wgt[NE * NTOK];
__device__ int   g_cnt[NE];
__device__ int   g_tokf[NE * CAP];
__device__ float g_wf[NE * CAP];
__device__ int   g_fincnt[NE];
__device__ int   g_fcnt[NE];
__device__ float g_psum[NE];
__device__ int   g_tilelist[NE * 8];             // active (e, m-tile) pairs
__device__ int   g_ntilel;
__device__ int   g_work2[2];                     // up / down work counters

// ---------------- common helpers ----------------
__device__ __forceinline__ uint32_t smem_u32(const void* p) {
    uint32_t a;
    asm("{ .reg .u64 t; cvta.to.shared.u64 t, %1; cvt.u32.u64 %0, t; }" : "=r"(a) : "l"(p));
    return a;
}
// bf16 pack (fallback path)
__device__ __forceinline__ unsigned bpack(float e0, float e1) {
    unsigned r;
    asm("cvt.rn.bf16x2.f32 %0, %1, %2;" : "=r"(r) : "f"(e1), "f"(e0));
    return r;
}
__device__ __forceinline__ float blo(unsigned h) { return __uint_as_float(h << 16); }
__device__ __forceinline__ float bhi(unsigned h) { return __uint_as_float(h & 0xffff0000u); }
__device__ __forceinline__ void hilo8(float4 v0, float4 v1, uint4& hi, uint4& lo) {
    hi.x = bpack(v0.x, v0.y); hi.y = bpack(v0.z, v0.w);
    hi.z = bpack(v1.x, v1.y); hi.w = bpack(v1.z, v1.w);
    lo.x = bpack(v0.x - blo(hi.x), v0.y - bhi(hi.x));
    lo.y = bpack(v0.z - blo(hi.y), v0.w - bhi(hi.y));
    lo.z = bpack(v1.x - blo(hi.z), v1.y - bhi(hi.z));
    lo.w = bpack(v1.z - blo(hi.w), v1.w - bhi(hi.w));
}
// fp16 pack + half extraction
__device__ __forceinline__ unsigned hpack(float e0, float e1) {
    unsigned r;
    asm("cvt.rn.f16x2.f32 %0, %1, %2;" : "=r"(r) : "f"(e1), "f"(e0));  // e1->hi, e0->lo
    return r;
}
__device__ __forceinline__ float hlo(unsigned h) {
    float f;
    asm("{ .reg .f16 l, hh; mov.b32 {l, hh}, %1; cvt.f32.f16 %0, l; }" : "=f"(f) : "r"(h));
    return f;
}
__device__ __forceinline__ float hhi(unsigned h) {
    float f;
    asm("{ .reg .f16 l, hh; mov.b32 {l, hh}, %1; cvt.f32.f16 %0, hh; }" : "=f"(f) : "r"(h));
    return f;
}
// A: fp16 hi/lo split (8 floats)
__device__ __forceinline__ void hilo8h(float4 v0, float4 v1, uint4& hi, uint4& lo) {
    hi.x = hpack(v0.x, v0.y); hi.y = hpack(v0.z, v0.w);
    hi.z = hpack(v1.x, v1.y); hi.w = hpack(v1.z, v1.w);
    lo.x = hpack(v0.x - hlo(hi.x), v0.y - hhi(hi.x));
    lo.y = hpack(v0.z - hlo(hi.y), v0.w - hhi(hi.y));
    lo.z = hpack(v1.x - hlo(hi.z), v1.y - hhi(hi.z));
    lo.w = hpack(v1.z - hlo(hi.w), v1.w - hhi(hi.w));
}
// B: single-fp16 pack (8 floats)
__device__ __forceinline__ uint4 pack8h(float4 v0, float4 v1) {
    uint4 r;
    r.x = hpack(v0.x, v0.y); r.y = hpack(v0.z, v0.w);
    r.z = hpack(v1.x, v1.y); r.w = hpack(v1.z, v1.w);
    return r;
}
__device__ __forceinline__ float gelu_f(float v) {
    return 0.5f * v * (1.f + erff(v * 0.70710678118654752f));
}

// ---- mma.sync fallback macros (base target legal) ----
#define LDSM4(R0, R1, R2, R3, ADDR) \
    asm volatile("ldmatrix.sync.aligned.m8n8.x4.shared.b16 {%0,%1,%2,%3}, [%4];" \
        : "=r"(R0), "=r"(R1), "=r"(R2), "=r"(R3) : "r"(ADDR))
#define MMA_BF16(C, A, B) \
    asm volatile("mma.sync.aligned.m16n8k16.row.col.f32.bf16.bf16.f32 " \
        "{%0,%1,%2,%3},{%4,%5,%6,%7},{%8,%9},{%0,%1,%2,%3};" \
        : "+f"((C)[0]), "+f"((C)[1]), "+f"((C)[2]), "+f"((C)[3]) \
        : "r"((A)[0]), "r"((A)[1]), "r"((A)[2]), "r"((A)[3]), "r"((B)[0]), "r"((B)[1]))

#define MBARRIER_INIT(addr, cnt) \
    asm volatile("mbarrier.init.shared.b64 [%0], %1;" :: "r"((uint32_t)(addr)), "r"((uint32_t)(cnt)) : "memory")
#define MBARRIER_WAIT_PARITY(addr, par) do { \
    uint32_t _m = (uint32_t)(addr); uint32_t _p = (uint32_t)(par); uint32_t _d; \
    asm volatile("{\n\t.reg .pred p;\n\tmbarrier.try_wait.parity.acquire.cta.shared::cta.b64 p, [%1], %2;\n\tselp.b32 %0, 1, 0, p;\n\t}" \
        : "=r"(_d) : "r"(_m), "r"(_p) : "memory"); \
    if (!_d) { \
        asm volatile("{\n\t.reg .pred P1;\n\tWL_%=:\n\tmbarrier.try_wait.parity.acquire.cta.shared::cta.b64 P1, [%0], %1, 0x989680;\n\t@P1 bra.uni WD_%=;\n\tbra.uni WL_%=;\n\tWD_%=:\n\t}" \
            :: "r"(_m), "r"(_p) : "memory"); \
    } } while (0)

#if defined(__CUDA_ARCH_FEAT_SM103_ALL)
__device__ __forceinline__ uint32_t elect_one_pred() {
    uint32_t pred;
    asm volatile("{\n\t.reg .pred p;\n\telect.sync _|p, 0xFFFFFFFF;\n\tselp.b32 %0, 1, 0, p;\n\t}" : "=r"(pred));
    return pred;
}
#define TCGEN05_ALLOC(sa, n)   asm volatile("tcgen05.alloc.cta_group::1.sync.aligned.shared::cta.b32 [%0], %1;" :: "r"((uint32_t)(sa)), "r"((uint32_t)(n)) : "memory")
#define TCGEN05_DEALLOC(t, n)  asm volatile("tcgen05.dealloc.cta_group::1.sync.aligned.b32 %0, %1;" :: "r"(t), "r"((uint32_t)(n)))
#define TCGEN05_RELINQ()       asm volatile("tcgen05.relinquish_alloc_permit.cta_group::1.sync.aligned;")
#define TCGEN05_COMMIT(mb)     asm volatile("tcgen05.commit.cta_group::1.mbarrier::arrive::one.shared::cluster.b64 [%0];" :: "r"((uint32_t)(mb)) : "memory")
#define TCGEN05_FENCE_AFTER()  asm volatile("tcgen05.fence::after_thread_sync;" ::: "memory")
#define TCGEN05_FENCE_BEFORE() asm volatile("tcgen05.fence::before_thread_sync;" ::: "memory")
#define TCGEN05_WAIT_LD()      asm volatile("tcgen05.wait::ld.sync.aligned;" ::: "memory")
#define FENCE_ASYNC_SHARED()   asm volatile("fence.proxy.async.shared::cta;" ::: "memory")
#define TCGEN05_LD_X32(r, ta) \
    asm volatile("tcgen05.ld.sync.aligned.32x32b.x32.b32 " \
        "{%0, %1, %2, %3, %4, %5, %6, %7, %8, %9, %10, %11, %12, %13, %14, %15, " \
        " %16, %17, %18, %19, %20, %21, %22, %23, %24, %25, %26, %27, %28, %29, %30, %31}, [%32];" \
        : "=r"((r)[0]), "=r"((r)[1]), "=r"((r)[2]), "=r"((r)[3]), "=r"((r)[4]), "=r"((r)[5]), "=r"((r)[6]), "=r"((r)[7]), \
          "=r"((r)[8]), "=r"((r)[9]), "=r"((r)[10]), "=r"((r)[11]), "=r"((r)[12]), "=r"((r)[13]), "=r"((r)[14]), "=r"((r)[15]), \
          "=r"((r)[16]), "=r"((r)[17]), "=r"((r)[18]), "=r"((r)[19]), "=r"((r)[20]), "=r"((r)[21]), "=r"((r)[22]), "=r"((r)[23]), \
          "=r"((r)[24]), "=r"((r)[25]), "=r"((r)[26]), "=r"((r)[27]), "=r"((r)[28]), "=r"((r)[29]), "=r"((r)[30]), "=r"((r)[31]) \
        : "r"(ta))
__device__ __forceinline__ void mma_ss_f16(uint32_t d, uint64_t a, uint64_t b, uint32_t idesc, uint32_t en) {
    asm volatile("{\n\t.reg .pred p;\n\tsetp.ne.u32 p, %5, 0;\n\t"
                 "tcgen05.mma.cta_group::1.kind::f16 [%0], %1, %2, %3, {%4, %4, %4, %4}, p;\n\t}"
                 :: "r"(d), "l"(a), "l"(b), "r"(idesc), "r"(0u), "r"(en) : "memory");
}
// SW64 K-major descriptor: layout=4, version=1, SBO=32 (512B atom), LBO=1
__device__ __forceinline__ uint64_t mk_desc64(uint32_t addr) {
    const uint64_t base = (uint64_t(4) << 61) | (uint64_t(1) << 46) | (uint64_t(32) << 32) | (uint64_t(1) << 16);
    return base | ((uint64_t)(addr >> 4) & 0x3FFF);
}
__device__ __forceinline__ uint32_t swz64(uint32_t o) { return o ^ ((o >> 3) & 0x30); }
__device__ __forceinline__ void red4(float* p, float a, float b, float c, float d) {
    asm volatile("red.global.add.v4.f32 [%0], {%1,%2,%3,%4};" :: "l"(p), "f"(a), "f"(b), "f"(c), "f"(d) : "memory");
}
#endif

// ---------------- K0: init counters (tiny) ----------------
__global__ void k_init() {
    if (threadIdx.x < NE) {
        g_cnt[threadIdx.x] = 0; g_fcnt[threadIdx.x] = 0;
        g_psum[threadIdx.x] = 0.f; g_fincnt[threadIdx.x] = 0;
    }
    if (threadIdx.x == 0) { g_ntilel = 0; g_work2[0] = 0; g_work2[1] = 0; }
}

// ---------------- K1: router (+ zero out) ----------------
__global__ __launch_bounds__(256) void k_router(const float* __restrict__ x,
                                                const float* __restrict__ Wr,
                                                const float* __restrict__ br,
                                                float* __restrict__ out) {
    __shared__ float sW[NE * HD];
    __shared__ float sP[NE];
    __shared__ int   sF[NE];
    int tid = threadIdx.x;
    {
        float4 z = {0.f, 0.f, 0.f, 0.f};
        float4* o4 = reinterpret_cast<float4*>(out) + (size_t)blockIdx.x * 2048 + tid;
#pragma unroll
        for (int i = 0; i < 8; i++) o4[i * 256] = z;
    }
    for (int i = tid; i < NE * HD; i += 256) sW[i] = Wr[i];
    if (tid < NE) { sP[tid] = 0.f; sF[tid] = 0; }
    __syncthreads();

    int warp = tid >> 5, lane = tid & 31;
    int t = blockIdx.x * 8 + warp;

    float acc[NE];
#pragma unroll
    for (int e = 0; e < NE; e++) acc[e] = 0.f;
    const float* xr = x + (size_t)t * HD;
    for (int h = lane; h < HD; h += 32) {
        float xv = xr[h];
#pragma unroll
        for (int e = 0; e < NE; e++) acc[e] += xv * sW[e * HD + h];
    }
#pragma unroll
    for (int e = 0; e < NE; e++) {
#pragma unroll
        for (int off = 16; off; off >>= 1)
            acc[e] += __shfl_down_sync(0xffffffffu, acc[e], off);
    }

    if (lane == 0) {
        float lg[NE];
#pragma unroll
        for (int e = 0; e < NE; e++) lg[e] = acc[e] + br[e];
        int e0 = 0;
#pragma unroll
        for (int e = 1; e < NE; e++) if (lg[e] > lg[e0]) e0 = e;
        int e1 = (e0 == 0) ? 1 : 0;
#pragma unroll
        for (int e = 0; e < NE; e++)
            if (e != e0 && lg[e] > lg[e1]) e1 = e;

        float mx = lg[e0], s = 0.f, p[NE];
#pragma unroll
        for (int e = 0; e < NE; e++) { p[e] = expf(lg[e] - mx); s += p[e]; }
        float inv = 1.f / s;
        atomicAdd(&sF[e0], 1);
#pragma unroll
        for (int e = 0; e < NE; e++) atomicAdd(&sP[e], p[e] * inv);

        float tt = expf(lg[e1] - lg[e0]);
        float r0 = 1.f / (1.f + tt);
        float r1 = tt / (1.f + tt);

        int s0 = atomicAdd(&g_cnt[e0], 1);
        g_tok[e0 * NTOK + s0] = t; g_wgt[e0 * NTOK + s0] = r0;
        int s1 = atomicAdd(&g_cnt[e1], 1);
        g_tok[e1 * NTOK + s1] = t; g_wgt[e1 * NTOK + s1] = r1;
    }
    __syncthreads();
    if (tid < NE) {
        atomicAdd(&g_psum[tid], sP[tid]);
        atomicAdd(&g_fcnt[tid], sF[tid]);
    }
}

// ---------------- K2: capacity trim + aux loss + tile list ----------------
__global__ void k_trim(float* out, int out_size) {
    int e = blockIdx.x;
    int tid = threadIdx.x;
    int cnt = g_cnt[e];
    int fin;
    if (cnt <= CAP) {
        for (int i = tid; i < cnt; i += blockDim.x) {
            g_tokf[e * CAP + i] = g_tok[e * NTOK + i];
            g_wf[e * CAP + i]   = g_wgt[e * NTOK + i];
        }
        fin = cnt;
        if (tid == 0) g_fincnt[e] = cnt;
    } else {
        __shared__ int sc;
        if (tid == 0) sc = 0;
        __syncthreads();
        for (int i = tid; i < cnt; i += blockDim.x) {
            float wi = g_wgt[e * NTOK + i];
            int   ti = g_tok[e * NTOK + i];
            int rank = 0;
            for (int j = 0; j < cnt; j++) {
                float wj = g_wgt[e * NTOK + j];
                int   tj = g_tok[e * NTOK + j];
                rank += (wj > wi) || (wj == wi && tj < ti);
            }
            if (rank < CAP) {
                int ppos = atomicAdd(&sc, 1);
                g_tokf[e * CAP + ppos] = ti;
                g_wf[e * CAP + ppos]   = wi;
            }
        }
        __syncthreads();
        fin = CAP;
        if (tid == 0) g_fincnt[e] = CAP;
    }
    if (tid == 0) {
        int nm = (fin + 255) >> 8;
        if (nm > 0) {
            int pos = atomicAdd(&g_ntilel, nm);
            for (int i = 0; i < nm; i++) g_tilelist[pos + i] = (e << 8) | i;
        }
    }
    if (blockIdx.x == 0 && tid == 0 && out_size > NTOK * HD) {
        float a = 0.f;
        for (int q = 0; q < NE; q++)
            a += ((float)g_fcnt[q] / (float)NTOK) * (g_psum[q] / (float)NTOK);
        out[NTOK * HD] = (float)NE * a * 0.001f;
    }
}

// ---------------- GEMM: persistent, 256x256 tiles, fp16 A-split x2 MMA -----
// stage s at 1024 + s*49152: Ahi(16K) Alo(16K) B(16K), SW64 rows (64B)
#define SMEM_GEMM (1024 + 2 * 49152)

template <bool IS_UP, int KDIM, int NDIM, int NSPLIT>
__global__ __launch_bounds__(512, 1) void k_moe_gemm(const float* __restrict__ xA,
                                                     const float* __restrict__ W,
                                                     const float* __restrict__ bias,
                                                     float* __restrict__ outp) {
    const int NTN = NDIM / 256;
    const int KLEN = KDIM / NSPLIT;
    extern __shared__ char smem[];
    uint32_t sb = smem_u32(smem);
    int tid = threadIdx.x, warp = tid >> 5, lane = tid & 31;

#if defined(__CUDA_ARCH_FEAT_SM103_ALL)
    // ================= tcgen05 persistent path =================
    if (tid == 0) { MBARRIER_INIT(sb + 8, 1); MBARRIER_INIT(sb + 16, 1); }
    if (warp == 0) { TCGEN05_ALLOC(sb + 0, 512); TCGEN05_RELINQ(); }
    __syncthreads();
    uint32_t tmem;
    asm volatile("ld.shared.b32 %0, [%1];" : "=r"(tmem) : "r"(sb + 0));

    // kind::f16, atype=btype=F16 (0), dtype=F32, N=256, M=128
    const uint32_t IDESC = (1u << 4) | (32u << 17) | (8u << 24);
    const int total = g_ntilel * NTN * NSPLIT;
    int r0 = tid >> 2, kq = tid & 3;
    uint32_t off0 = swz64((uint32_t)(r0 * 64 + kq * 16));
    uint32_t off1 = swz64((uint32_t)((r0 + 128) * 64 + kq * 16));

    int gkt = 0;
    int cc[2] = {0, 0};

    while (true) {
        if (tid == 0) {
            int w = atomicAdd(&g_work2[IS_UP ? 0 : 1], 1);
            *(int*)(smem + 32) = w;
        }
        __syncthreads();
        int w = *(int*)(smem + 32);
        if (w >= total) break;
        int n_i = w % NTN;
        int t2 = w / NTN;
        int kh = t2 % NSPLIT;
        int tl = g_tilelist[t2 / NSPLIT];
        int e = tl >> 8;
        int m0 = (tl & 255) * 256;
        int n0 = n_i * 256;
        int kbase = kh * KLEN;
        int cnt = g_fincnt[e];

        const float* aPtr[2];
        const float* bPtr[2];
#pragma unroll
        for (int i = 0; i < 2; i++) {
            int row = r0 + 128 * i, m = m0 + row;
            if (IS_UP) {
                int mm = (m < cnt) ? m : 0;
                int tok = g_tokf[e * CAP + mm];
                aPtr[i] = xA + (size_t)tok * KDIM + kbase + kq * 8;
            } else {
                aPtr[i] = g_h + ((size_t)e * CAP + m) * (size_t)KDIM + kbase + kq * 8;
            }
            bPtr[i] = W + (size_t)e * NDIM * KDIM + (size_t)(n0 + row) * KDIM + kbase + kq * 8;
        }

        float4 fa[2][2], fb[2][2];
#pragma unroll
        for (int i = 0; i < 2; i++) {
            fa[i][0] = *(const float4*)(aPtr[i]);
            fa[i][1] = *(const float4*)(aPtr[i] + 4);
            fb[i][0] = *(const float4*)(bPtr[i]);
            fb[i][1] = *(const float4*)(bPtr[i] + 4);
        }

        const int KT = KLEN / 32;
#pragma unroll 1
        for (int kt = 0; kt < KT; kt++) {
            int b = gkt & 1;
            if (gkt >= 2) MBARRIER_WAIT_PARITY(sb + 8 + 8 * b, (uint32_t)((cc[b] - 1) & 1));
            char* stg = smem + 1024 + b * 49152;
            int koff2 = (kt + 1) * 32;
            // A: fp16 hi/lo convert + store, then prefetch next A
            {
                uint4 hi, lo;
                hilo8h(fa[0][0], fa[0][1], hi, lo);
                *(uint4*)(stg + off0)         = hi;
                *(uint4*)(stg + 16384 + off0) = lo;
                hilo8h(fa[1][0], fa[1][1], hi, lo);
                *(uint4*)(stg + off1)         = hi;
                *(uint4*)(stg + 16384 + off1) = lo;
            }
            if (kt + 1 < KT) {
#pragma unroll
                for (int i = 0; i < 2; i++) {
                    fa[i][0] = *(const float4*)(aPtr[i] + koff2);
                    fa[i][1] = *(const float4*)(aPtr[i] + koff2 + 4);
                }
            }
            // B: single fp16 pack + store, then prefetch next B
            {
                *(uint4*)(stg + 32768 + off0) = pack8h(fb[0][0], fb[0][1]);
                *(uint4*)(stg + 32768 + off1) = pack8h(fb[1][0], fb[1][1]);
            }
            if (kt + 1 < KT) {
#pragma unroll
                for (int i = 0; i < 2; i++) {
                    fb[i][0] = *(const float4*)(bPtr[i] + koff2);
                    fb[i][1] = *(const float4*)(bPtr[i] + koff2 + 4);
                }
            }
            __syncthreads();
            if (warp == 0 && elect_one_pred()) {
                FENCE_ASYNC_SHARED();
                uint32_t sg = sb + 1024 + b * 49152;
                uint64_t dAh = mk_desc64(sg), dAl = mk_desc64(sg + 16384);
                uint64_t dB  = mk_desc64(sg + 32768);
#pragma unroll
                for (int h = 0; h < 2; h++) {
                    uint64_t ah = dAh + h * 512, al = dAl + h * 512;
                    uint32_t dst = tmem + h * 256;
#pragma unroll
                    for (int ks = 0; ks < 2; ks++) {
                        uint64_t o = (uint64_t)(ks * 2);
                        mma_ss_f16(dst, ah + o, dB + o, IDESC, !(kt == 0 && ks == 0));
                        mma_ss_f16(dst, al + o, dB + o, IDESC, 1u);
                    }
                }
                TCGEN05_COMMIT(sb + 8 + 8 * b);
            }
            cc[b]++;
            gkt++;
        }
        {
            int lb2 = (gkt - 1) & 1;
            MBARRIER_WAIT_PARITY(sb + 8 + 8 * lb2, (uint32_t)((cc[lb2] - 1) & 1));
        }
        TCGEN05_FENCE_AFTER();

        // epilogue (16 warps): sub = warp&3, g = warp>>2: hh = g&1, cg = g>>1
        int sub = warp & 3;
        int g  = warp >> 2;
        int hh = g & 1, cg = g >> 1;
        int m = m0 + hh * 128 + sub * 32 + lane;
        bool valid = m < cnt;
        int tok = 0;
        float wv = 0.f;
        float* orow;
        if (IS_UP) {
            orow = g_h + ((size_t)e * CAP + m) * (size_t)NDIM + n0;
        } else {
            if (valid) { tok = g_tokf[e * CAP + m]; wv = g_wf[e * CAP + m]; }
            orow = outp + (size_t)tok * HD + n0;
        }
#pragma unroll
        for (int bb = 0; bb < 4; bb++) {
            int c0 = cg * 128 + bb * 32;
            uint32_t d[32];
            TCGEN05_LD_X32(d, tmem + hh * 256 + c0);
            TCGEN05_WAIT_LD();
            if (valid) {
                const float* bptr = bias + (size_t)e * NDIM + n0 + c0;
                if (IS_UP) {
#pragma unroll
                    for (int q = 0; q < 8; q++) {
                        float4 bv = *(const float4*)(bptr + q * 4);
                        float4 o;
                        o.x = gelu_f(__uint_as_float(d[q * 4 + 0]) + bv.x);
                        o.y = gelu_f(__uint_as_float(d[q * 4 + 1]) + bv.y);
                        o.z = gelu_f(__uint_as_float(d[q * 4 + 2]) + bv.z);
                        o.w = gelu_f(__uint_as_float(d[q * 4 + 3]) + bv.w);
                        *(float4*)(orow + c0 + q * 4) = o;
                    }
                } else {
#pragma unroll
                    for (int q = 0; q < 8; q++) {
                        float4 bv = *(const float4*)(bptr + q * 4);
                        float b0 = (kh == 0) ? bv.x : 0.f;
                        float b1 = (kh == 0) ? bv.y : 0.f;
                        float b2 = (kh == 0) ? bv.z : 0.f;
                        float b3 = (kh == 0) ? bv.w : 0.f;
                        red4(orow + c0 + q * 4,
                             wv * (__uint_as_float(d[q * 4 + 0]) + b0),
                             wv * (__uint_as_float(d[q * 4 + 1]) + b1),
                             wv * (__uint_as_float(d[q * 4 + 2]) + b2),
                             wv * (__uint_as_float(d[q * 4 + 3]) + b3));
                    }
                }
            }
        }
        TCGEN05_FENCE_BEFORE();
        __syncthreads();
    }
    __syncthreads();
    if (warp == 0) TCGEN05_DEALLOC(tmem, 512);
#else
    // ================= mma.sync fallback (compute_103 PTX pass; correctness only)
    const int PITCH = 80;
    int rowf = tid & 127, hlf = (tid >> 7) & 1;
    bool active = tid < 256;
    uint32_t stOff = (uint32_t)(rowf * PITCH + hlf * 32);
    int wm = (warp >> 2) & 1, wn = warp & 3;
    const int total = g_ntilel * (NDIM / 256) * NSPLIT;

    while (true) {
        if (tid == 0) {
            int w = atomicAdd(&g_work2[IS_UP ? 0 : 1], 1);
            *(int*)(smem + 32) = w;
        }
        __syncthreads();
        int w = *(int*)(smem + 32);
        __syncthreads();
        if (w >= total) break;
        int NTN2 = NDIM / 256;
        int n_i = w % NTN2;
        int t2 = w / NTN2;
        int kh = t2 % NSPLIT;
        int tl = g_tilelist[t2 / NSPLIT];
        int e = tl >> 8;
        int m0 = (tl & 255) * 256;
        int n0 = n_i * 256;
        int kbase = kh * KLEN;
        int cnt = g_fincnt[e];

#pragma unroll 1
        for (int mh = 0; mh < 2; mh++) {
            int m0h = m0 + mh * 128;
            const float* aSrc;
            if (IS_UP) {
                int m = m0h + rowf;
                int mm = (m < cnt) ? m : 0;
                int tok = g_tokf[e * CAP + mm];
                aSrc = xA + (size_t)tok * KDIM + kbase + hlf * 16;
            } else {
                aSrc = g_h + ((size_t)e * CAP + m0h + rowf) * (size_t)KDIM + kbase + hlf * 16;
            }

#pragma unroll 1
            for (int hh2 = 0; hh2 < 2; hh2++) {
                int n0h = n0 + hh2 * 128;
                const float* bSrc = W + (size_t)e * NDIM * KDIM + (size_t)(n0h + rowf) * KDIM + kbase + hlf * 16;

                float acc[4][4][4];
#pragma unroll
                for (int i = 0; i < 4; i++)
#pragma unroll
                    for (int j = 0; j < 4; j++)
#pragma unroll
                        for (int q = 0; q < 4; q++) acc[i][j][q] = 0.f;

                float4 va0, va1, va2, va3, vb0, vb1, vb2, vb3;
                va0 = *(const float4*)(aSrc + 0);  va1 = *(const float4*)(aSrc + 4);
                va2 = *(const float4*)(aSrc + 8);  va3 = *(const float4*)(aSrc + 12);
                vb0 = *(const float4*)(bSrc + 0);  vb1 = *(const float4*)(bSrc + 4);
                vb2 = *(const float4*)(bSrc + 8);  vb3 = *(const float4*)(bSrc + 12);

                const int KT = KLEN / 32;
#pragma unroll 1
                for (int kt = 0; kt < KT; kt++) {
                    int b = kt & 1;
                    char* Sp = smem + 1024 + b * 40960;
                    uint32_t S = sb + 1024 + b * 40960;
                    uint4 h0, l0, h1, l1;
                    hilo8(va0, va1, h0, l0); hilo8(va2, va3, h1, l1);
                    *(uint4*)(Sp + stOff) = h0;           *(uint4*)(Sp + stOff + 16) = h1;
                    *(uint4*)(Sp + 10240 + stOff) = l0;   *(uint4*)(Sp + 10240 + stOff + 16) = l1;
                    hilo8(vb0, vb1, h0, l0); hilo8(vb2, vb3, h1, l1);
                    *(uint4*)(Sp + 20480 + stOff) = h0;   *(uint4*)(Sp + 20480 + stOff + 16) = h1;
                    *(uint4*)(Sp + 30720 + stOff) = l0;   *(uint4*)(Sp + 30720 + stOff + 16) = l1;
                    __syncthreads();
                    if (kt + 1 < KT) {
                        const float* a = aSrc + (kt + 1) * 32;
                        const float* bq = bSrc + (kt + 1) * 32;
                        va0 = *(const float4*)(a + 0);  va1 = *(const float4*)(a + 4);
                        va2 = *(const float4*)(a + 8);  va3 = *(const float4*)(a + 12);
                        vb0 = *(const float4*)(bq + 0); vb1 = *(const float4*)(bq + 4);
                        vb2 = *(const float4*)(bq + 8); vb3 = *(const float4*)(bq + 12);
                    }
                    if (active) {
#pragma unroll
                        for (int ks = 0; ks < 2; ks++) {
                            uint32_t kb = (uint32_t)(ks * 32);
                            uint32_t ah[4][4], al[4][4], bh[4][2], bl[4][2];
#pragma unroll
                            for (int i = 0; i < 4; i++) {
                                uint32_t ad = S + (uint32_t)((wm * 64 + i * 16 + (lane & 15)) * PITCH) + kb + ((lane >> 4) << 4);
                                LDSM4(ah[i][0], ah[i][1], ah[i][2], ah[i][3], ad);
                                LDSM4(al[i][0], al[i][1], al[i][2], al[i][3], ad + 10240);
                            }
#pragma unroll
                            for (int jp = 0; jp < 2; jp++) {
                                uint32_t bd = S + 20480
                                            + (uint32_t)((wn * 32 + jp * 16 + (lane & 7) + (((lane >> 4) & 1) << 3)) * PITCH)
                                            + kb + (((lane >> 3) & 1) << 4);
                                uint32_t q0, q1, q2, q3;
                                LDSM4(q0, q1, q2, q3, bd);
                                bh[2 * jp][0] = q0; bh[2 * jp][1] = q1;
                                bh[2 * jp + 1][0] = q2; bh[2 * jp + 1][1] = q3;
                                LDSM4(q0, q1, q2, q3, bd + 10240);
                                bl[2 * jp][0] = q0; bl[2 * jp][1] = q1;
                                bl[2 * jp + 1][0] = q2; bl[2 * jp + 1][1] = q3;
                            }
#pragma unroll
                            for (int i = 0; i < 4; i++)
#pragma unroll
                                for (int j = 0; j < 4; j++) {
                                    MMA_BF16(acc[i][j], ah[i], bh[j]);
                                    MMA_BF16(acc[i][j], ah[i], bl[j]);
                                    MMA_BF16(acc[i][j], al[i], bh[j]);
                                }
                        }
                    }
                }

                if (active) {
                    int g2 = lane >> 2, c2 = (lane & 3) * 2;
#pragma unroll
                    for (int i = 0; i < 4; i++) {
                        int rA = m0h + wm * 64 + i * 16 + g2;
                        int rB = rA + 8;
                        bool vA = rA < cnt, vB = rB < cnt;
                        if (IS_UP) {
                            float* pA = g_h + ((size_t)e * CAP + rA) * (size_t)NDIM;
                            float* pB = g_h + ((size_t)e * CAP + rB) * (size_t)NDIM;
#pragma unroll
                            for (int j = 0; j < 4; j++) {
                                int ccol = n0h + wn * 32 + j * 8 + c2;
                                float b0 = bias[(size_t)e * NDIM + ccol];
                                float b1 = bias[(size_t)e * NDIM + ccol + 1];
                                if (vA) {
                                    float2 o = {gelu_f(acc[i][j][0] + b0), gelu_f(acc[i][j][1] + b1)};
                                    *(float2*)(pA + ccol) = o;
                                }
                                if (vB) {
                                    float2 o = {gelu_f(acc[i][j][2] + b0), gelu_f(acc[i][j][3] + b1)};
                                    *(float2*)(pB + ccol) = o;
                                }
                            }
                        } else {
                            int tokA = 0, tokB = 0;
                            float wA = 0.f, wB = 0.f;
                            if (vA) { tokA = g_tokf[e * CAP + rA]; wA = g_wf[e * CAP + rA]; }
                            if (vB) { tokB = g_tokf[e * CAP + rB]; wB = g_wf[e * CAP + rB]; }
                            float* pA = outp + (size_t)tokA * HD;
                            float* pB = outp + (size_t)tokB * HD;
#pragma unroll
                            for (int j = 0; j < 4; j++) {
                                int ccol = n0h + wn * 32 + j * 8 + c2;
                                float b0 = (kh == 0) ? bias[(size_t)e * NDIM + ccol] : 0.f;
                                float b1 = (kh == 0) ? bias[(size_t)e * NDIM + ccol + 1] : 0.f;
                                if (vA) {
                                    atomicAdd(pA + ccol,     wA * (acc[i][j][0] + b0));
                                    atomicAdd(pA + ccol + 1, wA * (acc[i][j][1] + b1));
                                }
                                if (vB) {
                                    atomicAdd(pB + ccol,     wB * (acc[i][j][2] + b0));
                                    atomicAdd(pB + ccol + 1, wB * (acc[i][j][3] + b1));
                                }
                            }
                        }
                    }
                }
                __syncthreads();
            }
        }
    }
#endif
}

// ---------------- launch ----------------
extern "C" void kernel_launch(void* const* d_in, const int* in_sizes, int n_in,
                              void* d_out, int out_size) {
    const float* x   = (const float*)d_in[0];
    const float* Wr  = (const float*)d_in[1];
    const float* br  = (const float*)d_in[2];
    const float* Wup = (const float*)d_in[3];
    const float* bup = (const float*)d_in[4];
    const float* Wdn = (const float*)d_in[5];
    const float* bdn = (const float*)d_in[6];
    float* out = (float*)d_out;

    cudaFuncSetAttribute(k_moe_gemm<true, HD, FD, 1>, cudaFuncAttributeMaxDynamicSharedMemorySize, SMEM_GEMM);
    cudaFuncSetAttribute(k_moe_gemm<false, FD, HD, 4>, cudaFuncAttributeMaxDynamicSharedMemorySize, SMEM_GEMM);

    k_init<<<1, 32>>>();
    k_router<<<NTOK / 8, 256>>>(x, Wr, br, out);
    k_trim<<<NE, 256>>>(out, out_size);

    // persistent grids: one CTA per SM
    k_moe_gemm<true, HD, FD, 1><<<152, 512, SMEM_GEMM>>>(x, Wup, bup, nullptr);
    k_moe_gemm<false, FD, HD, 4><<<152, 512, SMEM_GEMM>>>(nullptr, Wdn, bdn, out);
}

// round 16
// speedup vs baseline: 1.0224x; 1.0224x over previous
#include <cuda_runtime.h>
#include <cuda_bf16.h>
#include <math.h>
#include <stdint.h>

#define NTOK 4096
#define NE   8
#define HD   1024
#define FD   4096
#define CAP  2048

// ---------------- scratch (device globals) ----------------
__device__ float g_h[(size_t)NE * CAP * FD];     // 256 MB intermediate gelu(up)
__device__ int   g_tok[NE * NTOK];
__device__ float g_wgt[NE * NTOK];
__device__ int   g_cnt[NE];
__device__ int   g_tokf[NE * CAP];
__device__ float g_wf[NE * CAP];
__device__ int   g_fincnt[NE];
__device__ int   g_fcnt[NE];
__device__ float g_psum[NE];
__device__ int   g_tilelist[NE * 8];
__device__ int   g_ntilel;
__device__ int   g_work2[2];

// ---------------- common helpers ----------------
__device__ __forceinline__ uint32_t smem_u32(const void* p) {
    uint32_t a;
    asm("{ .reg .u64 t; cvta.to.shared.u64 t, %1; cvt.u32.u64 %0, t; }" : "=r"(a) : "l"(p));
    return a;
}
// bf16 pack (fallback path)
__device__ __forceinline__ unsigned bpack(float e0, float e1) {
    unsigned r;
    asm("cvt.rn.bf16x2.f32 %0, %1, %2;" : "=r"(r) : "f"(e1), "f"(e0));
    return r;
}
__device__ __forceinline__ float blo(unsigned h) { return __uint_as_float(h << 16); }
__device__ __forceinline__ float bhi(unsigned h) { return __uint_as_float(h & 0xffff0000u); }
__device__ __forceinline__ void hilo8(float4 v0, float4 v1, uint4& hi, uint4& lo) {
    hi.x = bpack(v0.x, v0.y); hi.y = bpack(v0.z, v0.w);
    hi.z = bpack(v1.x, v1.y); hi.w = bpack(v1.z, v1.w);
    lo.x = bpack(v0.x - blo(hi.x), v0.y - bhi(hi.x));
    lo.y = bpack(v0.z - blo(hi.y), v0.w - bhi(hi.y));
    lo.z = bpack(v1.x - blo(hi.z), v1.y - bhi(hi.z));
    lo.w = bpack(v1.z - blo(hi.w), v1.w - bhi(hi.w));
}
// fp16 pack + half extraction
__device__ __forceinline__ unsigned hpack(float e0, float e1) {
    unsigned r;
    asm("cvt.rn.f16x2.f32 %0, %1, %2;" : "=r"(r) : "f"(e1), "f"(e0));  // e1->hi, e0->lo
    return r;
}
__device__ __forceinline__ float hlo(unsigned h) {
    float f;
    asm("{ .reg .f16 l, hh; mov.b32 {l, hh}, %1; cvt.f32.f16 %0, l; }" : "=f"(f) : "r"(h));
    return f;
}
__device__ __forceinline__ float hhi(unsigned h) {
    float f;
    asm("{ .reg .f16 l, hh; mov.b32 {l, hh}, %1; cvt.f32.f16 %0, hh; }" : "=f"(f) : "r"(h));
    return f;
}
__device__ __forceinline__ void hilo8h(float4 v0, float4 v1, uint4& hi, uint4& lo) {
    hi.x = hpack(v0.x, v0.y); hi.y = hpack(v0.z, v0.w);
    hi.z = hpack(v1.x, v1.y); hi.w = hpack(v1.z, v1.w);
    lo.x = hpack(v0.x - hlo(hi.x), v0.y - hhi(hi.x));
    lo.y = hpack(v0.z - hlo(hi.y), v0.w - hhi(hi.y));
    lo.z = hpack(v1.x - hlo(hi.z), v1.y - hhi(hi.z));
    lo.w = hpack(v1.z - hlo(hi.w), v1.w - hhi(hi.w));
}
__device__ __forceinline__ uint4 pack8h(float4 v0, float4 v1) {
    uint4 r;
    r.x = hpack(v0.x, v0.y); r.y = hpack(v0.z, v0.w);
    r.z = hpack(v1.x, v1.y); r.w = hpack(v1.z, v1.w);
    return r;
}
__device__ __forceinline__ float gelu_f(float v) {
    return 0.5f * v * (1.f + erff(v * 0.70710678118654752f));
}

// ---- mma.sync fallback macros ----
#define LDSM4(R0, R1, R2, R3, ADDR) \
    asm volatile("ldmatrix.sync.aligned.m8n8.x4.shared.b16 {%0,%1,%2,%3}, [%4];" \
        : "=r"(R0), "=r"(R1), "=r"(R2), "=r"(R3) : "r"(ADDR))
#define MMA_BF16(C, A, B) \
    asm volatile("mma.sync.aligned.m16n8k16.row.col.f32.bf16.bf16.f32 " \
        "{%0,%1,%2,%3},{%4,%5,%6,%7},{%8,%9},{%0,%1,%2,%3};" \
        : "+f"((C)[0]), "+f"((C)[1]), "+f"((C)[2]), "+f"((C)[3]) \
        : "r"((A)[0]), "r"((A)[1]), "r"((A)[2]), "r"((A)[3]), "r"((B)[0]), "r"((B)[1]))

#define MBARRIER_INIT(addr, cnt) \
    asm volatile("mbarrier.init.shared.b64 [%0], %1;" :: "r"((uint32_t)(addr)), "r"((uint32_t)(cnt)) : "memory")
#define MBARRIER_WAIT_PARITY(addr, par) do { \
    uint32_t _m = (uint32_t)(addr); uint32_t _p = (uint32_t)(par); uint32_t _d; \
    asm volatile("{\n\t.reg .pred p;\n\tmbarrier.try_wait.parity.acquire.cta.shared::cta.b64 p, [%1], %2;\n\tselp.b32 %0, 1, 0, p;\n\t}" \
        : "=r"(_d) : "r"(_m), "r"(_p) : "memory"); \
    if (!_d) { \
        asm volatile("{\n\t.reg .pred P1;\n\tWL_%=:\n\tmbarrier.try_wait.parity.acquire.cta.shared::cta.b64 P1, [%0], %1, 0x989680;\n\t@P1 bra.uni WD_%=;\n\tbra.uni WL_%=;\n\tWD_%=:\n\t}" \
            :: "r"(_m), "r"(_p) : "memory"); \
    } } while (0)

#if defined(__CUDA_ARCH_FEAT_SM103_ALL)
__device__ __forceinline__ uint32_t elect_one_pred() {
    uint32_t pred;
    asm volatile("{\n\t.reg .pred p;\n\telect.sync _|p, 0xFFFFFFFF;\n\tselp.b32 %0, 1, 0, p;\n\t}" : "=r"(pred));
    return pred;
}
#define TCGEN05_ALLOC(sa, n)   asm volatile("tcgen05.alloc.cta_group::1.sync.aligned.shared::cta.b32 [%0], %1;" :: "r"((uint32_t)(sa)), "r"((uint32_t)(n)) : "memory")
#define TCGEN05_DEALLOC(t, n)  asm volatile("tcgen05.dealloc.cta_group::1.sync.aligned.b32 %0, %1;" :: "r"(t), "r"((uint32_t)(n)))
#define TCGEN05_RELINQ()       asm volatile("tcgen05.relinquish_alloc_permit.cta_group::1.sync.aligned;")
#define TCGEN05_COMMIT(mb)     asm volatile("tcgen05.commit.cta_group::1.mbarrier::arrive::one.shared::cluster.b64 [%0];" :: "r"((uint32_t)(mb)) : "memory")
#define TCGEN05_FENCE_AFTER()  asm volatile("tcgen05.fence::after_thread_sync;" ::: "memory")
#define TCGEN05_FENCE_BEFORE() asm volatile("tcgen05.fence::before_thread_sync;" ::: "memory")
#define TCGEN05_WAIT_LD()      asm volatile("tcgen05.wait::ld.sync.aligned;" ::: "memory")
#define FENCE_ASYNC_SHARED()   asm volatile("fence.proxy.async.shared::cta;" ::: "memory")
#define TCGEN05_LD_X32(r, ta) \
    asm volatile("tcgen05.ld.sync.aligned.32x32b.x32.b32 " \
        "{%0, %1, %2, %3, %4, %5, %6, %7, %8, %9, %10, %11, %12, %13, %14, %15, " \
        " %16, %17, %18, %19, %20, %21, %22, %23, %24, %25, %26, %27, %28, %29, %30, %31}, [%32];" \
        : "=r"((r)[0]), "=r"((r)[1]), "=r"((r)[2]), "=r"((r)[3]), "=r"((r)[4]), "=r"((r)[5]), "=r"((r)[6]), "=r"((r)[7]), \
          "=r"((r)[8]), "=r"((r)[9]), "=r"((r)[10]), "=r"((r)[11]), "=r"((r)[12]), "=r"((r)[13]), "=r"((r)[14]), "=r"((r)[15]), \
          "=r"((r)[16]), "=r"((r)[17]), "=r"((r)[18]), "=r"((r)[19]), "=r"((r)[20]), "=r"((r)[21]), "=r"((r)[22]), "=r"((r)[23]), \
          "=r"((r)[24]), "=r"((r)[25]), "=r"((r)[26]), "=r"((r)[27]), "=r"((r)[28]), "=r"((r)[29]), "=r"((r)[30]), "=r"((r)[31]) \
        : "r"(ta))
__device__ __forceinline__ void mma_ss_f16(uint32_t d, uint64_t a, uint64_t b, uint32_t idesc, uint32_t en) {
    asm volatile("{\n\t.reg .pred p;\n\tsetp.ne.u32 p, %5, 0;\n\t"
                 "tcgen05.mma.cta_group::1.kind::f16 [%0], %1, %2, %3, {%4, %4, %4, %4}, p;\n\t}"
                 :: "r"(d), "l"(a), "l"(b), "r"(idesc), "r"(0u), "r"(en) : "memory");
}
// SW128 K-major descriptor: layout=2, version=1, SBO=64 (1024B atom), LBO=1 (proven R3-R5)
__device__ __forceinline__ uint64_t mk_desc128(uint32_t addr) {
    const uint64_t base = (uint64_t(2) << 61) | (uint64_t(1) << 46) | (uint64_t(64) << 32) | (uint64_t(1) << 16);
    return base | ((uint64_t)(addr >> 4) & 0x3FFF);
}
__device__ __forceinline__ uint32_t swz128(uint32_t o) { return o ^ ((o >> 3) & 0x70); }
__device__ __forceinline__ void red4(float* p, float a, float b, float c, float d) {
    asm volatile("red.global.add.v4.f32 [%0], {%1,%2,%3,%4};" :: "l"(p), "f"(a), "f"(b), "f"(c), "f"(d) : "memory");
}
#endif

// ---------------- K0: init counters ----------------
__global__ void k_init() {
    if (threadIdx.x < NE) {
        g_cnt[threadIdx.x] = 0; g_fcnt[threadIdx.x] = 0;
        g_psum[threadIdx.x] = 0.f; g_fincnt[threadIdx.x] = 0;
    }
    if (threadIdx.x == 0) { g_ntilel = 0; g_work2[0] = 0; g_work2[1] = 0; }
}

// ---------------- K1: router (+ zero out) ----------------
__global__ __launch_bounds__(256) void k_router(const float* __restrict__ x,
                                                const float* __restrict__ Wr,
                                                const float* __restrict__ br,
                                                float* __restrict__ out) {
    __shared__ float sW[NE * HD];
    __shared__ float sP[NE];
    __shared__ int   sF[NE];
    int tid = threadIdx.x;
    {
        float4 z = {0.f, 0.f, 0.f, 0.f};
        float4* o4 = reinterpret_cast<float4*>(out) + (size_t)blockIdx.x * 2048 + tid;
#pragma unroll
        for (int i = 0; i < 8; i++) o4[i * 256] = z;
    }
    for (int i = tid; i < NE * HD; i += 256) sW[i] = Wr[i];
    if (tid < NE) { sP[tid] = 0.f; sF[tid] = 0; }
    __syncthreads();

    int warp = tid >> 5, lane = tid & 31;
    int t = blockIdx.x * 8 + warp;

    float acc[NE];
#pragma unroll
    for (int e = 0; e < NE; e++) acc[e] = 0.f;
    const float* xr = x + (size_t)t * HD;
    for (int h = lane; h < HD; h += 32) {
        float xv = xr[h];
#pragma unroll
        for (int e = 0; e < NE; e++) acc[e] += xv * sW[e * HD + h];
    }
#pragma unroll
    for (int e = 0; e < NE; e++) {
#pragma unroll
        for (int off = 16; off; off >>= 1)
            acc[e] += __shfl_down_sync(0xffffffffu, acc[e], off);
    }

    if (lane == 0) {
        float lg[NE];
#pragma unroll
        for (int e = 0; e < NE; e++) lg[e] = acc[e] + br[e];
        int e0 = 0;
#pragma unroll
        for (int e = 1; e < NE; e++) if (lg[e] > lg[e0]) e0 = e;
        int e1 = (e0 == 0) ? 1 : 0;
#pragma unroll
        for (int e = 0; e < NE; e++)
            if (e != e0 && lg[e] > lg[e1]) e1 = e;

        float mx = lg[e0], s = 0.f, p[NE];
#pragma unroll
        for (int e = 0; e < NE; e++) { p[e] = expf(lg[e] - mx); s += p[e]; }
        float inv = 1.f / s;
        atomicAdd(&sF[e0], 1);
#pragma unroll
        for (int e = 0; e < NE; e++) atomicAdd(&sP[e], p[e] * inv);

        float tt = expf(lg[e1] - lg[e0]);
        float r0 = 1.f / (1.f + tt);
        float r1 = tt / (1.f + tt);

        int s0 = atomicAdd(&g_cnt[e0], 1);
        g_tok[e0 * NTOK + s0] = t; g_wgt[e0 * NTOK + s0] = r0;
        int s1 = atomicAdd(&g_cnt[e1], 1);
        g_tok[e1 * NTOK + s1] = t; g_wgt[e1 * NTOK + s1] = r1;
    }
    __syncthreads();
    if (tid < NE) {
        atomicAdd(&g_psum[tid], sP[tid]);
        atomicAdd(&g_fcnt[tid], sF[tid]);
    }
}

// ---------------- K2: trim + aux loss + tile list ----------------
__global__ void k_trim(float* out, int out_size) {
    int e = blockIdx.x;
    int tid = threadIdx.x;
    int cnt = g_cnt[e];
    int fin;
    if (cnt <= CAP) {
        for (int i = tid; i < cnt; i += blockDim.x) {
            g_tokf[e * CAP + i] = g_tok[e * NTOK + i];
            g_wf[e * CAP + i]   = g_wgt[e * NTOK + i];
        }
        fin = cnt;
        if (tid == 0) g_fincnt[e] = cnt;
    } else {
        __shared__ int sc;
        if (tid == 0) sc = 0;
        __syncthreads();
        for (int i = tid; i < cnt; i += blockDim.x) {
            float wi = g_wgt[e * NTOK + i];
            int   ti = g_tok[e * NTOK + i];
            int rank = 0;
            for (int j = 0; j < cnt; j++) {
                float wj = g_wgt[e * NTOK + j];
                int   tj = g_tok[e * NTOK + j];
                rank += (wj > wi) || (wj == wi && tj < ti);
            }
            if (rank < CAP) {
                int ppos = atomicAdd(&sc, 1);
                g_tokf[e * CAP + ppos] = ti;
                g_wf[e * CAP + ppos]   = wi;
            }
        }
        __syncthreads();
        fin = CAP;
        if (tid == 0) g_fincnt[e] = CAP;
    }
    if (tid == 0) {
        int nm = (fin + 255) >> 8;
        if (nm > 0) {
            int pos = atomicAdd(&g_ntilel, nm);
            for (int i = 0; i < nm; i++) g_tilelist[pos + i] = (e << 8) | i;
        }
    }
    if (blockIdx.x == 0 && tid == 0 && out_size > NTOK * HD) {
        float a = 0.f;
        for (int q = 0; q < NE; q++)
            a += ((float)g_fcnt[q] / (float)NTOK) * (g_psum[q] / (float)NTOK);
        out[NTOK * HD] = (float)NE * a * 0.001f;
    }
}

// ---------------- GEMM: persistent, 256x256 tiles, fp16 A-split x2, BK=64 --
// stage s at 1024 + s*98304: Ahi(32K) Alo(32K) B(32K), SW128 rows (128B)
#define SMEM_GEMM (1024 + 2 * 98304)

template <bool IS_UP, int KDIM, int NDIM, int NSPLIT>
__global__ __launch_bounds__(512, 1) void k_moe_gemm(const float* __restrict__ xA,
                                                     const float* __restrict__ W,
                                                     const float* __restrict__ bias,
                                                     float* __restrict__ outp) {
    const int NTN = NDIM / 256;
    const int KLEN = KDIM / NSPLIT;
    extern __shared__ char smem[];
    uint32_t sb = smem_u32(smem);
    int tid = threadIdx.x, warp = tid >> 5, lane = tid & 31;

#if defined(__CUDA_ARCH_FEAT_SM103_ALL)
    // ================= tcgen05 persistent path =================
    if (tid == 0) { MBARRIER_INIT(sb + 8, 1); MBARRIER_INIT(sb + 16, 1); }
    if (warp == 0) { TCGEN05_ALLOC(sb + 0, 512); TCGEN05_RELINQ(); }
    __syncthreads();
    uint32_t tmem;
    asm volatile("ld.shared.b32 %0, [%1];" : "=r"(tmem) : "r"(sb + 0));

    // kind::f16, atype=btype=F16, dtype=F32, N=256, M=128
    const uint32_t IDESC = (1u << 4) | (32u << 17) | (8u << 24);
    const int total = g_ntilel * NTN * NSPLIT;
    // BK=64: rows 256, 128B rows; thread t: row r0 = t>>3 (+64i), slot kq = t&7 (16B)
    int r0 = tid >> 3, kq = tid & 7;
    uint32_t offr[4];
#pragma unroll
    for (int i = 0; i < 4; i++)
        offr[i] = swz128((uint32_t)((r0 + 64 * i) * 128 + kq * 16));

    int gkt = 0;
    int cc[2] = {0, 0};

    while (true) {
        if (tid == 0) {
            int w = atomicAdd(&g_work2[IS_UP ? 0 : 1], 1);
            *(int*)(smem + 32) = w;
        }
        __syncthreads();
        int w = *(int*)(smem + 32);
        if (w >= total) break;
        int n_i = w % NTN;
        int t2 = w / NTN;
        int kh = t2 % NSPLIT;
        int tl = g_tilelist[t2 / NSPLIT];
        int e = tl >> 8;
        int m0 = (tl & 255) * 256;
        int n0 = n_i * 256;
        int kbase = kh * KLEN;
        int cnt = g_fincnt[e];

        const float* aPtr[4];
        const float* bPtr[4];
#pragma unroll
        for (int i = 0; i < 4; i++) {
            int row = r0 + 64 * i, m = m0 + row;
            if (IS_UP) {
                int mm = (m < cnt) ? m : 0;
                int tok = g_tokf[e * CAP + mm];
                aPtr[i] = xA + (size_t)tok * KDIM + kbase + kq * 8;
            } else {
                aPtr[i] = g_h + ((size_t)e * CAP + m) * (size_t)KDIM + kbase + kq * 8;
            }
            bPtr[i] = W + (size_t)e * NDIM * KDIM + (size_t)(n0 + row) * KDIM + kbase + kq * 8;
        }

        float4 fa[4][2], fb[4][2];
#pragma unroll
        for (int i = 0; i < 4; i++) {
            fa[i][0] = *(const float4*)(aPtr[i]);
            fa[i][1] = *(const float4*)(aPtr[i] + 4);
            fb[i][0] = *(const float4*)(bPtr[i]);
            fb[i][1] = *(const float4*)(bPtr[i] + 4);
        }

        const int KT = KLEN / 64;
#pragma unroll 1
        for (int kt = 0; kt < KT; kt++) {
            int b = gkt & 1;
            if (gkt >= 2) MBARRIER_WAIT_PARITY(sb + 8 + 8 * b, (uint32_t)((cc[b] - 1) & 1));
            char* stg = smem + 1024 + b * 98304;
            int koff2 = (kt + 1) * 64;
            // A: fp16 hi/lo convert + store, then prefetch next A (proven ordering)
#pragma unroll
            for (int i = 0; i < 4; i++) {
                uint4 hi, lo;
                hilo8h(fa[i][0], fa[i][1], hi, lo);
                *(uint4*)(stg + offr[i])         = hi;
                *(uint4*)(stg + 32768 + offr[i]) = lo;
            }
            if (kt + 1 < KT) {
#pragma unroll
                for (int i = 0; i < 4; i++) {
                    fa[i][0] = *(const float4*)(aPtr[i] + koff2);
                    fa[i][1] = *(const float4*)(aPtr[i] + koff2 + 4);
                }
            }
            // B: single fp16 pack + store, then prefetch next B
#pragma unroll
            for (int i = 0; i < 4; i++)
                *(uint4*)(stg + 65536 + offr[i]) = pack8h(fb[i][0], fb[i][1]);
            if (kt + 1 < KT) {
#pragma unroll
                for (int i = 0; i < 4; i++) {
                    fb[i][0] = *(const float4*)(bPtr[i] + koff2);
                    fb[i][1] = *(const float4*)(bPtr[i] + koff2 + 4);
                }
            }
            __syncthreads();
            if (warp == 0 && elect_one_pred()) {
                FENCE_ASYNC_SHARED();
                uint32_t sg = sb + 1024 + b * 98304;
                uint64_t dAh = mk_desc128(sg), dAl = mk_desc128(sg + 32768);
                uint64_t dB  = mk_desc128(sg + 65536);
#pragma unroll
                for (int h = 0; h < 2; h++) {
                    uint64_t ah = dAh + h * 1024, al = dAl + h * 1024; // +128 rows*128B = 1024 units
                    uint32_t dst = tmem + h * 256;
#pragma unroll
                    for (int ks = 0; ks < 4; ks++) {
                        uint64_t o = (uint64_t)(ks * 2);  // 16 fp16 = 32B = 2 units
                        mma_ss_f16(dst, ah + o, dB + o, IDESC, !(kt == 0 && ks == 0));
                        mma_ss_f16(dst, al + o, dB + o, IDESC, 1u);
                    }
                }
                TCGEN05_COMMIT(sb + 8 + 8 * b);
            }
            cc[b]++;
            gkt++;
        }
        {
            int lb2 = (gkt - 1) & 1;
            MBARRIER_WAIT_PARITY(sb + 8 + 8 * lb2, (uint32_t)((cc[lb2] - 1) & 1));
        }
        TCGEN05_FENCE_AFTER();

        // epilogue (16 warps): sub = warp&3, g = warp>>2: hh = g&1, cg = g>>1
        int sub = warp & 3;
        int g  = warp >> 2;
        int hh = g & 1, cg = g >> 1;
        int m = m0 + hh * 128 + sub * 32 + lane;
        bool valid = m < cnt;
        int tok = 0;
        float wv = 0.f;
        float* orow;
        if (IS_UP) {
            orow = g_h + ((size_t)e * CAP + m) * (size_t)NDIM + n0;
        } else {
            if (valid) { tok = g_tokf[e * CAP + m]; wv = g_wf[e * CAP + m]; }
            orow = outp + (size_t)tok * HD + n0;
        }
#pragma unroll
        for (int bb = 0; bb < 4; bb++) {
            int c0 = cg * 128 + bb * 32;
            uint32_t d[32];
            TCGEN05_LD_X32(d, tmem + hh * 256 + c0);
            TCGEN05_WAIT_LD();
            if (valid) {
                const float* bptr = bias + (size_t)e * NDIM + n0 + c0;
                if (IS_UP) {
#pragma unroll
                    for (int q = 0; q < 8; q++) {
                        float4 bv = *(const float4*)(bptr + q * 4);
                        float4 o;
                        o.x = gelu_f(__uint_as_float(d[q * 4 + 0]) + bv.x);
                        o.y = gelu_f(__uint_as_float(d[q * 4 + 1]) + bv.y);
                        o.z = gelu_f(__uint_as_float(d[q * 4 + 2]) + bv.z);
                        o.w = gelu_f(__uint_as_float(d[q * 4 + 3]) + bv.w);
                        *(float4*)(orow + c0 + q * 4) = o;
                    }
                } else {
#pragma unroll
                    for (int q = 0; q < 8; q++) {
                        float4 bv = *(const float4*)(bptr + q * 4);
                        float b0 = (kh == 0) ? bv.x : 0.f;
                        float b1 = (kh == 0) ? bv.y : 0.f;
                        float b2 = (kh == 0) ? bv.z : 0.f;
                        float b3 = (kh == 0) ? bv.w : 0.f;
                        red4(orow + c0 + q * 4,
                             wv * (__uint_as_float(d[q * 4 + 0]) + b0),
                             wv * (__uint_as_float(d[q * 4 + 1]) + b1),
                             wv * (__uint_as_float(d[q * 4 + 2]) + b2),
                             wv * (__uint_as_float(d[q * 4 + 3]) + b3));
                    }
                }
            }
        }
        TCGEN05_FENCE_BEFORE();
        __syncthreads();
    }
    __syncthreads();
    if (warp == 0) TCGEN05_DEALLOC(tmem, 512);
#else
    // ================= mma.sync fallback (compute_103 PTX pass; correctness only)
    const int PITCH = 80;
    int rowf = tid & 127, hlf = (tid >> 7) & 1;
    bool active = tid < 256;
    uint32_t stOff = (uint32_t)(rowf * PITCH + hlf * 32);
    int wm = (warp >> 2) & 1, wn = warp & 3;
    const int total = g_ntilel * (NDIM / 256) * NSPLIT;

    while (true) {
        if (tid == 0) {
            int w = atomicAdd(&g_work2[IS_UP ? 0 : 1], 1);
            *(int*)(smem + 32) = w;
        }
        __syncthreads();
        int w = *(int*)(smem + 32);
        __syncthreads();
        if (w >= total) break;
        int NTN2 = NDIM / 256;
        int n_i = w % NTN2;
        int t2 = w / NTN2;
        int kh = t2 % NSPLIT;
        int tl = g_tilelist[t2 / NSPLIT];
        int e = tl >> 8;
        int m0 = (tl & 255) * 256;
        int n0 = n_i * 256;
        int kbase = kh * KLEN;
        int cnt = g_fincnt[e];

#pragma unroll 1
        for (int mh = 0; mh < 2; mh++) {
            int m0h = m0 + mh * 128;
            const float* aSrc;
            if (IS_UP) {
                int m = m0h + rowf;
                int mm = (m < cnt) ? m : 0;
                int tok = g_tokf[e * CAP + mm];
                aSrc = xA + (size_t)tok * KDIM + kbase + hlf * 16;
            } else {
                aSrc = g_h + ((size_t)e * CAP + m0h + rowf) * (size_t)KDIM + kbase + hlf * 16;
            }

#pragma unroll 1
            for (int hh2 = 0; hh2 < 2; hh2++) {
                int n0h = n0 + hh2 * 128;
                const float* bSrc = W + (size_t)e * NDIM * KDIM + (size_t)(n0h + rowf) * KDIM + kbase + hlf * 16;

                float acc[4][4][4];
#pragma unroll
                for (int i = 0; i < 4; i++)
#pragma unroll
                    for (int j = 0; j < 4; j++)
#pragma unroll
                        for (int q = 0; q < 4; q++) acc[i][j][q] = 0.f;

                float4 va0, va1, va2, va3, vb0, vb1, vb2, vb3;
                va0 = *(const float4*)(aSrc + 0);  va1 = *(const float4*)(aSrc + 4);
                va2 = *(const float4*)(aSrc + 8);  va3 = *(const float4*)(aSrc + 12);
                vb0 = *(const float4*)(bSrc + 0);  vb1 = *(const float4*)(bSrc + 4);
                vb2 = *(const float4*)(bSrc + 8);  vb3 = *(const float4*)(bSrc + 12);

                const int KT = KLEN / 32;
#pragma unroll 1
                for (int kt = 0; kt < KT; kt++) {
                    int b = kt & 1;
                    char* Sp = smem + 1024 + b * 40960;
                    uint32_t S = sb + 1024 + b * 40960;
                    uint4 h0, l0, h1, l1;
                    hilo8(va0, va1, h0, l0); hilo8(va2, va3, h1, l1);
                    *(uint4*)(Sp + stOff) = h0;           *(uint4*)(Sp + stOff + 16) = h1;
                    *(uint4*)(Sp + 10240 + stOff) = l0;   *(uint4*)(Sp + 10240 + stOff + 16) = l1;
                    hilo8(vb0, vb1, h0, l0); hilo8(vb2, vb3, h1, l1);
                    *(uint4*)(Sp + 20480 + stOff) = h0;   *(uint4*)(Sp + 20480 + stOff + 16) = h1;
                    *(uint4*)(Sp + 30720 + stOff) = l0;   *(uint4*)(Sp + 30720 + stOff + 16) = l1;
                    __syncthreads();
                    if (kt + 1 < KT) {
                        const float* a = aSrc + (kt + 1) * 32;
                        const float* bq = bSrc + (kt + 1) * 32;
                        va0 = *(const float4*)(a + 0);  va1 = *(const float4*)(a + 4);
                        va2 = *(const float4*)(a + 8);  va3 = *(const float4*)(a + 12);
                        vb0 = *(const float4*)(bq + 0); vb1 = *(const float4*)(bq + 4);
                        vb2 = *(const float4*)(bq + 8); vb3 = *(const float4*)(bq + 12);
                    }
                    if (active) {
#pragma unroll
                        for (int ks = 0; ks < 2; ks++) {
                            uint32_t kb = (uint32_t)(ks * 32);
                            uint32_t ah[4][4], al[4][4], bh[4][2], bl[4][2];
#pragma unroll
                            for (int i = 0; i < 4; i++) {
                                uint32_t ad = S + (uint32_t)((wm * 64 + i * 16 + (lane & 15)) * PITCH) + kb + ((lane >> 4) << 4);
                                LDSM4(ah[i][0], ah[i][1], ah[i][2], ah[i][3], ad);
                                LDSM4(al[i][0], al[i][1], al[i][2], al[i][3], ad + 10240);
                            }
#pragma unroll
                            for (int jp = 0; jp < 2; jp++) {
                                uint32_t bd = S + 20480
                                            + (uint32_t)((wn * 32 + jp * 16 + (lane & 7) + (((lane >> 4) & 1) << 3)) * PITCH)
                                            + kb + (((lane >> 3) & 1) << 4);
                                uint32_t q0, q1, q2, q3;
                                LDSM4(q0, q1, q2, q3, bd);
                                bh[2 * jp][0] = q0; bh[2 * jp][1] = q1;
                                bh[2 * jp + 1][0] = q2; bh[2 * jp + 1][1] = q3;
                                LDSM4(q0, q1, q2, q3, bd + 10240);
                                bl[2 * jp][0] = q0; bl[2 * jp][1] = q1;
                                bl[2 * jp + 1][0] = q2; bl[2 * jp + 1][1] = q3;
                            }
#pragma unroll
                            for (int i = 0; i < 4; i++)
#pragma unroll
                                for (int j = 0; j < 4; j++) {
                                    MMA_BF16(acc[i][j], ah[i], bh[j]);
                                    MMA_BF16(acc[i][j], ah[i], bl[j]);
                                    MMA_BF16(acc[i][j], al[i], bh[j]);
                                }
                        }
                    }
                }

                if (active) {
                    int g2 = lane >> 2, c2 = (lane & 3) * 2;
#pragma unroll
                    for (int i = 0; i < 4; i++) {
                        int rA = m0h + wm * 64 + i * 16 + g2;
                        int rB = rA + 8;
                        bool vA = rA < cnt, vB = rB < cnt;
                        if (IS_UP) {
                            float* pA = g_h + ((size_t)e * CAP + rA) * (size_t)NDIM;
                            float* pB = g_h + ((size_t)e * CAP + rB) * (size_t)NDIM;
#pragma unroll
                            for (int j = 0; j < 4; j++) {
                                int ccol = n0h + wn * 32 + j * 8 + c2;
                                float b0 = bias[(size_t)e * NDIM + ccol];
                                float b1 = bias[(size_t)e * NDIM + ccol + 1];
                                if (vA) {
                                    float2 o = {gelu_f(acc[i][j][0] + b0), gelu_f(acc[i][j][1] + b1)};
                                    *(float2*)(pA + ccol) = o;
                                }
                                if (vB) {
                                    float2 o = {gelu_f(acc[i][j][2] + b0), gelu_f(acc[i][j][3] + b1)};
                                    *(float2*)(pB + ccol) = o;
                                }
                            }
                        } else {
                            int tokA = 0, tokB = 0;
                            float wA = 0.f, wB = 0.f;
                            if (vA) { tokA = g_tokf[e * CAP + rA]; wA = g_wf[e * CAP + rA]; }
                            if (vB) { tokB = g_tokf[e * CAP + rB]; wB = g_wf[e * CAP + rB]; }
                            float* pA = outp + (size_t)tokA * HD;
                            float* pB = outp + (size_t)tokB * HD;
#pragma unroll
                            for (int j = 0; j < 4; j++) {
                                int ccol = n0h + wn * 32 + j * 8 + c2;
                                float b0 = (kh == 0) ? bias[(size_t)e * NDIM + ccol] : 0.f;
                                float b1 = (kh == 0) ? bias[(size_t)e * NDIM + ccol + 1] : 0.f;
                                if (vA) {
                                    atomicAdd(pA + ccol,     wA * (acc[i][j][0] + b0));
                                    atomicAdd(pA + ccol + 1, wA * (acc[i][j][1] + b1));
                                }
                                if (vB) {
                                    atomicAdd(pB + ccol,     wB * (acc[i][j][2] + b0));
                                    atomicAdd(pB + ccol + 1, wB * (acc[i][j][3] + b1));
                                }
                            }
                        }
                    }
                }
                __syncthreads();
            }
        }
    }
#endif
}

// ---------------- launch ----------------
extern "C" void kernel_launch(void* const* d_in, const int* in_sizes, int n_in,
                              void* d_out, int out_size) {
    const float* x   = (const float*)d_in[0];
    const float* Wr  = (const float*)d_in[1];
    const float* br  = (const float*)d_in[2];
    const float* Wup = (const float*)d_in[3];
    const float* bup = (const float*)d_in[4];
    const float* Wdn = (const float*)d_in[5];
    const float* bdn = (const float*)d_in[6];
    float* out = (float*)d_out;

    cudaFuncSetAttribute(k_moe_gemm<true, HD, FD, 1>, cudaFuncAttributeMaxDynamicSharedMemorySize, SMEM_GEMM);
    cudaFuncSetAttribute(k_moe_gemm<false, FD, HD, 4>, cudaFuncAttributeMaxDynamicSharedMemorySize, SMEM_GEMM);

    k_init<<<1, 32>>>();
    k_router<<<NTOK / 8, 256>>>(x, Wr, br, out);
    k_trim<<<NE, 256>>>(out, out_size);

    k_moe_gemm<true, HD, FD, 1><<<152, 512, SMEM_GEMM>>>(x, Wup, bup, nullptr);
    k_moe_gemm<false, FD, HD, 4><<<152, 512, SMEM_GEMM>>>(nullptr, Wdn, bdn, out);
}

// round 17
// speedup vs baseline: 1.1661x; 1.1405x over previous
#include <cuda_runtime.h>
#include <cuda_bf16.h>
#include <cuda_fp16.h>
#include <math.h>
#include <stdint.h>

#define NTOK 4096
#define NE   8
#define HD   1024
#define FD   4096
#define CAP  2048

// ---------------- scratch (device globals) ----------------
__device__ __half g_h[(size_t)NE * CAP * FD];    // 128 MB intermediate gelu(up), fp16
__device__ int   g_tok[NE * NTOK];
__device__ float g_wgt[NE * NTOK];
__device__ int   g_cnt[NE];
__device__ int   g_tokf[NE * CAP];
__device__ float g_wf[NE * CAP];
__device__ int   g_fincnt[NE];
__device__ int   g_fcnt[NE];
__device__ float g_psum[NE];
__device__ int   g_tilelist[NE * 8];
__device__ int   g_ntilel;
__device__ int   g_work2[2];

// ---------------- common helpers ----------------
__device__ __forceinline__ uint32_t smem_u32(const void* p) {
    uint32_t a;
    asm("{ .reg .u64 t; cvta.to.shared.u64 t, %1; cvt.u32.u64 %0, t; }" : "=r"(a) : "l"(p));
    return a;
}
// bf16 pack
__device__ __forceinline__ unsigned bpack(float e0, float e1) {
    unsigned r;
    asm("cvt.rn.bf16x2.f32 %0, %1, %2;" : "=r"(r) : "f"(e1), "f"(e0));
    return r;
}
__device__ __forceinline__ float blo(unsigned h) { return __uint_as_float(h << 16); }
__device__ __forceinline__ float bhi(unsigned h) { return __uint_as_float(h & 0xffff0000u); }
__device__ __forceinline__ void hilo8(float4 v0, float4 v1, uint4& hi, uint4& lo) {
    hi.x = bpack(v0.x, v0.y); hi.y = bpack(v0.z, v0.w);
    hi.z = bpack(v1.x, v1.y); hi.w = bpack(v1.z, v1.w);
    lo.x = bpack(v0.x - blo(hi.x), v0.y - bhi(hi.x));
    lo.y = bpack(v0.z - blo(hi.y), v0.w - bhi(hi.y));
    lo.z = bpack(v1.x - blo(hi.z), v1.y - bhi(hi.z));
    lo.w = bpack(v1.z - blo(hi.w), v1.w - bhi(hi.w));
}
// fp16 pack
__device__ __forceinline__ unsigned hpack(float e0, float e1) {
    unsigned r;
    asm("cvt.rn.f16x2.f32 %0, %1, %2;" : "=r"(r) : "f"(e1), "f"(e0));  // e1->hi, e0->lo (mem: e0 first)
    return r;
}
__device__ __forceinline__ uint4 pack8h(float4 v0, float4 v1) {
    uint4 r;
    r.x = hpack(v0.x, v0.y); r.y = hpack(v0.z, v0.w);
    r.z = hpack(v1.x, v1.y); r.w = hpack(v1.z, v1.w);
    return r;
}
__device__ __forceinline__ float gelu_f(float v) {
    return 0.5f * v * (1.f + erff(v * 0.70710678118654752f));
}

// ---- mma.sync fallback macros ----
#define LDSM4(R0, R1, R2, R3, ADDR) \
    asm volatile("ldmatrix.sync.aligned.m8n8.x4.shared.b16 {%0,%1,%2,%3}, [%4];" \
        : "=r"(R0), "=r"(R1), "=r"(R2), "=r"(R3) : "r"(ADDR))
#define MMA_BF16(C, A, B) \
    asm volatile("mma.sync.aligned.m16n8k16.row.col.f32.bf16.bf16.f32 " \
        "{%0,%1,%2,%3},{%4,%5,%6,%7},{%8,%9},{%0,%1,%2,%3};" \
        : "+f"((C)[0]), "+f"((C)[1]), "+f"((C)[2]), "+f"((C)[3]) \
        : "r"((A)[0]), "r"((A)[1]), "r"((A)[2]), "r"((A)[3]), "r"((B)[0]), "r"((B)[1]))

#define MBARRIER_INIT(addr, cnt) \
    asm volatile("mbarrier.init.shared.b64 [%0], %1;" :: "r"((uint32_t)(addr)), "r"((uint32_t)(cnt)) : "memory")
#define MBARRIER_WAIT_PARITY(addr, par) do { \
    uint32_t _m = (uint32_t)(addr); uint32_t _p = (uint32_t)(par); uint32_t _d; \
    asm volatile("{\n\t.reg .pred p;\n\tmbarrier.try_wait.parity.acquire.cta.shared::cta.b64 p, [%1], %2;\n\tselp.b32 %0, 1, 0, p;\n\t}" \
        : "=r"(_d) : "r"(_m), "r"(_p) : "memory"); \
    if (!_d) { \
        asm volatile("{\n\t.reg .pred P1;\n\tWL_%=:\n\tmbarrier.try_wait.parity.acquire.cta.shared::cta.b64 P1, [%0], %1, 0x989680;\n\t@P1 bra.uni WD_%=;\n\tbra.uni WL_%=;\n\tWD_%=:\n\t}" \
            :: "r"(_m), "r"(_p) : "memory"); \
    } } while (0)

#if defined(__CUDA_ARCH_FEAT_SM103_ALL)
__device__ __forceinline__ uint32_t elect_one_pred() {
    uint32_t pred;
    asm volatile("{\n\t.reg .pred p;\n\telect.sync _|p, 0xFFFFFFFF;\n\tselp.b32 %0, 1, 0, p;\n\t}" : "=r"(pred));
    return pred;
}
#define TCGEN05_ALLOC(sa, n)   asm volatile("tcgen05.alloc.cta_group::1.sync.aligned.shared::cta.b32 [%0], %1;" :: "r"((uint32_t)(sa)), "r"((uint32_t)(n)) : "memory")
#define TCGEN05_DEALLOC(t, n)  asm volatile("tcgen05.dealloc.cta_group::1.sync.aligned.b32 %0, %1;" :: "r"(t), "r"((uint32_t)(n)))
#define TCGEN05_RELINQ()       asm volatile("tcgen05.relinquish_alloc_permit.cta_group::1.sync.aligned;")
#define TCGEN05_COMMIT(mb)     asm volatile("tcgen05.commit.cta_group::1.mbarrier::arrive::one.shared::cluster.b64 [%0];" :: "r"((uint32_t)(mb)) : "memory")
#define TCGEN05_FENCE_AFTER()  asm volatile("tcgen05.fence::after_thread_sync;" ::: "memory")
#define TCGEN05_FENCE_BEFORE() asm volatile("tcgen05.fence::before_thread_sync;" ::: "memory")
#define TCGEN05_WAIT_LD()      asm volatile("tcgen05.wait::ld.sync.aligned;" ::: "memory")
#define FENCE_ASYNC_SHARED()   asm volatile("fence.proxy.async.shared::cta;" ::: "memory")
#define TCGEN05_LD_X32(r, ta) \
    asm volatile("tcgen05.ld.sync.aligned.32x32b.x32.b32 " \
        "{%0, %1, %2, %3, %4, %5, %6, %7, %8, %9, %10, %11, %12, %13, %14, %15, " \
        " %16, %17, %18, %19, %20, %21, %22, %23, %24, %25, %26, %27, %28, %29, %30, %31}, [%32];" \
        : "=r"((r)[0]), "=r"((r)[1]), "=r"((r)[2]), "=r"((r)[3]), "=r"((r)[4]), "=r"((r)[5]), "=r"((r)[6]), "=r"((r)[7]), \
          "=r"((r)[8]), "=r"((r)[9]), "=r"((r)[10]), "=r"((r)[11]), "=r"((r)[12]), "=r"((r)[13]), "=r"((r)[14]), "=r"((r)[15]), \
          "=r"((r)[16]), "=r"((r)[17]), "=r"((r)[18]), "=r"((r)[19]), "=r"((r)[20]), "=r"((r)[21]), "=r"((r)[22]), "=r"((r)[23]), \
          "=r"((r)[24]), "=r"((r)[25]), "=r"((r)[26]), "=r"((r)[27]), "=r"((r)[28]), "=r"((r)[29]), "=r"((r)[30]), "=r"((r)[31]) \
        : "r"(ta))
__device__ __forceinline__ void mma_ss_f16k(uint32_t d, uint64_t a, uint64_t b, uint32_t idesc, uint32_t en) {
    asm volatile("{\n\t.reg .pred p;\n\tsetp.ne.u32 p, %5, 0;\n\t"
                 "tcgen05.mma.cta_group::1.kind::f16 [%0], %1, %2, %3, {%4, %4, %4, %4}, p;\n\t}"
                 :: "r"(d), "l"(a), "l"(b), "r"(idesc), "r"(0u), "r"(en) : "memory");
}
// SW64 K-major descriptor: layout=4, version=1, SBO=32 (512B atom), LBO=1
__device__ __forceinline__ uint64_t mk_desc64(uint32_t addr) {
    const uint64_t base = (uint64_t(4) << 61) | (uint64_t(1) << 46) | (uint64_t(32) << 32) | (uint64_t(1) << 16);
    return base | ((uint64_t)(addr >> 4) & 0x3FFF);
}
__device__ __forceinline__ uint32_t swz64(uint32_t o) { return o ^ ((o >> 3) & 0x30); }
__device__ __forceinline__ void red4(float* p, float a, float b, float c, float d) {
    asm volatile("red.global.add.v4.f32 [%0], {%1,%2,%3,%4};" :: "l"(p), "f"(a), "f"(b), "f"(c), "f"(d) : "memory");
}
#endif

// ---------------- K0: init counters ----------------
__global__ void k_init() {
    if (threadIdx.x < NE) {
        g_cnt[threadIdx.x] = 0; g_fcnt[threadIdx.x] = 0;
        g_psum[threadIdx.x] = 0.f; g_fincnt[threadIdx.x] = 0;
    }
    if (threadIdx.x == 0) { g_ntilel = 0; g_work2[0] = 0; g_work2[1] = 0; }
}

// ---------------- K1: router (+ zero out) ----------------
__global__ __launch_bounds__(256) void k_router(const float* __restrict__ x,
                                                const float* __restrict__ Wr,
                                                const float* __restrict__ br,
                                                float* __restrict__ out) {
    __shared__ float sW[NE * HD];
    __shared__ float sP[NE];
    __shared__ int   sF[NE];
    int tid = threadIdx.x;
    {
        float4 z = {0.f, 0.f, 0.f, 0.f};
        float4* o4 = reinterpret_cast<float4*>(out) + (size_t)blockIdx.x * 2048 + tid;
#pragma unroll
        for (int i = 0; i < 8; i++) o4[i * 256] = z;
    }
    for (int i = tid; i < NE * HD; i += 256) sW[i] = Wr[i];
    if (tid < NE) { sP[tid] = 0.f; sF[tid] = 0; }
    __syncthreads();

    int warp = tid >> 5, lane = tid & 31;
    int t = blockIdx.x * 8 + warp;

    float acc[NE];
#pragma unroll
    for (int e = 0; e < NE; e++) acc[e] = 0.f;
    const float* xr = x + (size_t)t * HD;
    for (int h = lane; h < HD; h += 32) {
        float xv = xr[h];
#pragma unroll
        for (int e = 0; e < NE; e++) acc[e] += xv * sW[e * HD + h];
    }
#pragma unroll
    for (int e = 0; e < NE; e++) {
#pragma unroll
        for (int off = 16; off; off >>= 1)
            acc[e] += __shfl_down_sync(0xffffffffu, acc[e], off);
    }

    if (lane == 0) {
        float lg[NE];
#pragma unroll
        for (int e = 0; e < NE; e++) lg[e] = acc[e] + br[e];
        int e0 = 0;
#pragma unroll
        for (int e = 1; e < NE; e++) if (lg[e] > lg[e0]) e0 = e;
        int e1 = (e0 == 0) ? 1 : 0;
#pragma unroll
        for (int e = 0; e < NE; e++)
            if (e != e0 && lg[e] > lg[e1]) e1 = e;

        float mx = lg[e0], s = 0.f, p[NE];
#pragma unroll
        for (int e = 0; e < NE; e++) { p[e] = expf(lg[e] - mx); s += p[e]; }
        float inv = 1.f / s;
        atomicAdd(&sF[e0], 1);
#pragma unroll
        for (int e = 0; e < NE; e++) atomicAdd(&sP[e], p[e] * inv);

        float tt = expf(lg[e1] - lg[e0]);
        float r0 = 1.f / (1.f + tt);
        float r1 = tt / (1.f + tt);

        int s0 = atomicAdd(&g_cnt[e0], 1);
        g_tok[e0 * NTOK + s0] = t; g_wgt[e0 * NTOK + s0] = r0;
        int s1 = atomicAdd(&g_cnt[e1], 1);
        g_tok[e1 * NTOK + s1] = t; g_wgt[e1 * NTOK + s1] = r1;
    }
    __syncthreads();
    if (tid < NE) {
        atomicAdd(&g_psum[tid], sP[tid]);
        atomicAdd(&g_fcnt[tid], sF[tid]);
    }
}

// ---------------- K2: trim + aux loss + tile list ----------------
__global__ void k_trim(float* out, int out_size) {
    int e = blockIdx.x;
    int tid = threadIdx.x;
    int cnt = g_cnt[e];
    int fin;
    if (cnt <= CAP) {
        for (int i = tid; i < cnt; i += blockDim.x) {
            g_tokf[e * CAP + i] = g_tok[e * NTOK + i];
            g_wf[e * CAP + i]   = g_wgt[e * NTOK + i];
        }
        fin = cnt;
        if (tid == 0) g_fincnt[e] = cnt;
    } else {
        __shared__ int sc;
        if (tid == 0) sc = 0;
        __syncthreads();
        for (int i = tid; i < cnt; i += blockDim.x) {
            float wi = g_wgt[e * NTOK + i];
            int   ti = g_tok[e * NTOK + i];
            int rank = 0;
            for (int j = 0; j < cnt; j++) {
                float wj = g_wgt[e * NTOK + j];
                int   tj = g_tok[e * NTOK + j];
                rank += (wj > wi) || (wj == wi && tj < ti);
            }
            if (rank < CAP) {
                int ppos = atomicAdd(&sc, 1);
                g_tokf[e * CAP + ppos] = ti;
                g_wf[e * CAP + ppos]   = wi;
            }
        }
        __syncthreads();
        fin = CAP;
        if (tid == 0) g_fincnt[e] = CAP;
    }
    if (tid == 0) {
        int nm = (fin + 255) >> 8;
        if (nm > 0) {
            int pos = atomicAdd(&g_ntilel, nm);
            for (int i = 0; i < nm; i++) g_tilelist[pos + i] = (e << 8) | i;
        }
    }
    if (blockIdx.x == 0 && tid == 0 && out_size > NTOK * HD) {
        float a = 0.f;
        for (int q = 0; q < NE; q++)
            a += ((float)g_fcnt[q] / (float)NTOK) * (g_psum[q] / (float)NTOK);
        out[NTOK * HD] = (float)NE * a * 0.001f;
    }
}

// ---------------- GEMM: persistent, 256x256 tiles -----------------
// up: bf16 hi/lo x3 (A=x fp32, B=Wup fp32), epilogue stores g_h as fp16
// down: single-pass fp16 (A=g_h fp16 direct copy, B=Wdn fp32->fp16)
// stage s at 1024 + s*65536; SW64 rows (64B)
#define SMEM_GEMM 132096

template <bool IS_UP, int KDIM, int NDIM, int NSPLIT>
__global__ __launch_bounds__(512, 1) void k_moe_gemm(const float* __restrict__ xA,
                                                     const float* __restrict__ W,
                                                     const float* __restrict__ bias,
                                                     float* __restrict__ outp) {
    const int NTN = NDIM / 256;
    const int KLEN = KDIM / NSPLIT;
    extern __shared__ char smem[];
    uint32_t sb = smem_u32(smem);
    int tid = threadIdx.x, warp = tid >> 5, lane = tid & 31;

#if defined(__CUDA_ARCH_FEAT_SM103_ALL)
    // ================= tcgen05 persistent path =================
    if (tid == 0) { MBARRIER_INIT(sb + 8, 1); MBARRIER_INIT(sb + 16, 1); }
    if (warp == 0) { TCGEN05_ALLOC(sb + 0, 512); TCGEN05_RELINQ(); }
    __syncthreads();
    uint32_t tmem;
    asm volatile("ld.shared.b32 %0, [%1];" : "=r"(tmem) : "r"(sb + 0));

    const uint32_t IDESC_BF = (1u << 4) | (1u << 7) | (1u << 10) | (32u << 17) | (8u << 24);
    const uint32_t IDESC_H  = (1u << 4) | (32u << 17) | (8u << 24);
    const int total = g_ntilel * NTN * NSPLIT;
    int r0 = tid >> 2, kq = tid & 3;
    uint32_t off0 = swz64((uint32_t)(r0 * 64 + kq * 16));
    uint32_t off1 = swz64((uint32_t)((r0 + 128) * 64 + kq * 16));

    int gkt = 0;
    int cc[2] = {0, 0};

    while (true) {
        if (tid == 0) {
            int w = atomicAdd(&g_work2[IS_UP ? 0 : 1], 1);
            *(int*)(smem + 32) = w;
        }
        __syncthreads();
        int w = *(int*)(smem + 32);
        if (w >= total) break;
        int n_i = w % NTN;
        int t2 = w / NTN;
        int kh = t2 % NSPLIT;
        int tl = g_tilelist[t2 / NSPLIT];
        int e = tl >> 8;
        int m0 = (tl & 255) * 256;
        int n0 = n_i * 256;
        int kbase = kh * KLEN;
        int cnt = g_fincnt[e];

        const float* bPtr[2];
#pragma unroll
        for (int i = 0; i < 2; i++) {
            int row = r0 + 128 * i;
            bPtr[i] = W + (size_t)e * NDIM * KDIM + (size_t)(n0 + row) * KDIM + kbase + kq * 8;
        }
        float4 fb[2][2];
#pragma unroll
        for (int i = 0; i < 2; i++) {
            fb[i][0] = *(const float4*)(bPtr[i]);
            fb[i][1] = *(const float4*)(bPtr[i] + 4);
        }

        if (IS_UP) {
            // ---------- up: bf16 hi/lo x3 ----------
            const float* aPtr[2];
#pragma unroll
            for (int i = 0; i < 2; i++) {
                int m = m0 + r0 + 128 * i;
                int mm = (m < cnt) ? m : 0;
                int tok = g_tokf[e * CAP + mm];
                aPtr[i] = xA + (size_t)tok * KDIM + kbase + kq * 8;
            }
            float4 fa[2][2];
#pragma unroll
            for (int i = 0; i < 2; i++) {
                fa[i][0] = *(const float4*)(aPtr[i]);
                fa[i][1] = *(const float4*)(aPtr[i] + 4);
            }
            const int KT = KLEN / 32;
#pragma unroll 1
            for (int kt = 0; kt < KT; kt++) {
                int b = gkt & 1;
                if (gkt >= 2) MBARRIER_WAIT_PARITY(sb + 8 + 8 * b, (uint32_t)((cc[b] - 1) & 1));
                char* stg = smem + 1024 + b * 65536;
                int koff2 = (kt + 1) * 32;
                {
                    uint4 hi, lo;
                    hilo8(fa[0][0], fa[0][1], hi, lo);
                    *(uint4*)(stg + off0)         = hi;
                    *(uint4*)(stg + 16384 + off0) = lo;
                    hilo8(fa[1][0], fa[1][1], hi, lo);
                    *(uint4*)(stg + off1)         = hi;
                    *(uint4*)(stg + 16384 + off1) = lo;
                }
                if (kt + 1 < KT) {
#pragma unroll
                    for (int i = 0; i < 2; i++) {
                        fa[i][0] = *(const float4*)(aPtr[i] + koff2);
                        fa[i][1] = *(const float4*)(aPtr[i] + koff2 + 4);
                    }
                }
                {
                    uint4 hi, lo;
                    hilo8(fb[0][0], fb[0][1], hi, lo);
                    *(uint4*)(stg + 32768 + off0) = hi;
                    *(uint4*)(stg + 49152 + off0) = lo;
                    hilo8(fb[1][0], fb[1][1], hi, lo);
                    *(uint4*)(stg + 32768 + off1) = hi;
                    *(uint4*)(stg + 49152 + off1) = lo;
                }
                if (kt + 1 < KT) {
#pragma unroll
                    for (int i = 0; i < 2; i++) {
                        fb[i][0] = *(const float4*)(bPtr[i] + koff2);
                        fb[i][1] = *(const float4*)(bPtr[i] + koff2 + 4);
                    }
                }
                __syncthreads();
                if (warp == 0 && elect_one_pred()) {
                    FENCE_ASYNC_SHARED();
                    uint32_t sg = sb + 1024 + b * 65536;
                    uint64_t dAh = mk_desc64(sg), dAl = mk_desc64(sg + 16384);
                    uint64_t dBh = mk_desc64(sg + 32768), dBl = mk_desc64(sg + 49152);
#pragma unroll
                    for (int h = 0; h < 2; h++) {
                        uint64_t ah = dAh + h * 512, al = dAl + h * 512;
                        uint32_t dst = tmem + h * 256;
#pragma unroll
                        for (int ks = 0; ks < 2; ks++) {
                            uint64_t o = (uint64_t)(ks * 2);
                            mma_ss_f16k(dst, ah + o, dBh + o, IDESC_BF, !(kt == 0 && ks == 0));
                            mma_ss_f16k(dst, ah + o, dBl + o, IDESC_BF, 1u);
                            mma_ss_f16k(dst, al + o, dBh + o, IDESC_BF, 1u);
                        }
                    }
                    TCGEN05_COMMIT(sb + 8 + 8 * b);
                }
                cc[b]++;
                gkt++;
            }
        } else {
            // ---------- down: single-pass fp16 (A = g_h fp16 direct) ----------
            const __half* aPtrH[2];
#pragma unroll
            for (int i = 0; i < 2; i++) {
                int m = m0 + r0 + 128 * i;
                aPtrH[i] = g_h + ((size_t)e * CAP + m) * (size_t)KDIM + kbase + kq * 8;
            }
            uint4 ua[2];
#pragma unroll
            for (int i = 0; i < 2; i++) ua[i] = *(const uint4*)(aPtrH[i]);  // 8 halfs? 16B = 8 halfs
            const int KT = KLEN / 32;
#pragma unroll 1
            for (int kt = 0; kt < KT; kt++) {
                int b = gkt & 1;
                if (gkt >= 2) MBARRIER_WAIT_PARITY(sb + 8 + 8 * b, (uint32_t)((cc[b] - 1) & 1));
                char* stg = smem + 1024 + b * 65536;
                int koff2 = (kt + 1) * 32;
                // A: direct fp16 copy — but 16B = 8 halfs covers only half the 16-half slot.
                // Slot kq*16B in a 64B row maps to halfs kq*8 of 32 — consistent: row=32 halfs, slot=8 halfs=16B. OK.
                *(uint4*)(stg + off0) = ua[0];
                *(uint4*)(stg + off1) = ua[1];
                if (kt + 1 < KT) {
#pragma unroll
                    for (int i = 0; i < 2; i++) ua[i] = *(const uint4*)(aPtrH[i] + koff2);
                }
                // B: fp32 -> single fp16 plane
                *(uint4*)(stg + 16384 + off0) = pack8h(fb[0][0], fb[0][1]);
                *(uint4*)(stg + 16384 + off1) = pack8h(fb[1][0], fb[1][1]);
                if (kt + 1 < KT) {
#pragma unroll
                    for (int i = 0; i < 2; i++) {
                        fb[i][0] = *(const float4*)(bPtr[i] + koff2);
                        fb[i][1] = *(const float4*)(bPtr[i] + koff2 + 4);
                    }
                }
                __syncthreads();
                if (warp == 0 && elect_one_pred()) {
                    FENCE_ASYNC_SHARED();
                    uint32_t sg = sb + 1024 + b * 65536;
                    uint64_t dA = mk_desc64(sg);
                    uint64_t dB = mk_desc64(sg + 16384);
#pragma unroll
                    for (int h = 0; h < 2; h++) {
                        uint64_t ah = dA + h * 512;
                        uint32_t dst = tmem + h * 256;
#pragma unroll
                        for (int ks = 0; ks < 2; ks++) {
                            uint64_t o = (uint64_t)(ks * 2);
                            mma_ss_f16k(dst, ah + o, dB + o, IDESC_H, !(kt == 0 && ks == 0));
                        }
                    }
                    TCGEN05_COMMIT(sb + 8 + 8 * b);
                }
                cc[b]++;
                gkt++;
            }
        }
        {
            int lb2 = (gkt - 1) & 1;
            MBARRIER_WAIT_PARITY(sb + 8 + 8 * lb2, (uint32_t)((cc[lb2] - 1) & 1));
        }
        TCGEN05_FENCE_AFTER();

        // epilogue (16 warps): sub = warp&3, g = warp>>2: hh = g&1, cg = g>>1
        int sub = warp & 3;
        int g  = warp >> 2;
        int hh = g & 1, cg = g >> 1;
        int m = m0 + hh * 128 + sub * 32 + lane;
        bool valid = m < cnt;
        int tok = 0;
        float wv = 0.f;
        __half* orowh = nullptr;
        float* orow = nullptr;
        if (IS_UP) {
            orowh = g_h + ((size_t)e * CAP + m) * (size_t)NDIM + n0;
        } else {
            if (valid) { tok = g_tokf[e * CAP + m]; wv = g_wf[e * CAP + m]; }
            orow = outp + (size_t)tok * HD + n0;
        }
#pragma unroll
        for (int bb = 0; bb < 4; bb++) {
            int c0 = cg * 128 + bb * 32;
            uint32_t d[32];
            TCGEN05_LD_X32(d, tmem + hh * 256 + c0);
            TCGEN05_WAIT_LD();
            if (valid) {
                const float* bptr = bias + (size_t)e * NDIM + n0 + c0;
                if (IS_UP) {
#pragma unroll
                    for (int q = 0; q < 8; q++) {
                        float4 bv = *(const float4*)(bptr + q * 4);
                        float v0 = gelu_f(__uint_as_float(d[q * 4 + 0]) + bv.x);
                        float v1 = gelu_f(__uint_as_float(d[q * 4 + 1]) + bv.y);
                        float v2 = gelu_f(__uint_as_float(d[q * 4 + 2]) + bv.z);
                        float v3 = gelu_f(__uint_as_float(d[q * 4 + 3]) + bv.w);
                        uint2 st;
                        st.x = hpack(v0, v1);
                        st.y = hpack(v2, v3);
                        *(uint2*)(orowh + c0 + q * 4) = st;
                    }
                } else {
#pragma unroll
                    for (int q = 0; q < 8; q++) {
                        float4 bv = *(const float4*)(bptr + q * 4);
                        float b0 = (kh == 0) ? bv.x : 0.f;
                        float b1 = (kh == 0) ? bv.y : 0.f;
                        float b2 = (kh == 0) ? bv.z : 0.f;
                        float b3 = (kh == 0) ? bv.w : 0.f;
                        red4(orow + c0 + q * 4,
                             wv * (__uint_as_float(d[q * 4 + 0]) + b0),
                             wv * (__uint_as_float(d[q * 4 + 1]) + b1),
                             wv * (__uint_as_float(d[q * 4 + 2]) + b2),
                             wv * (__uint_as_float(d[q * 4 + 3]) + b3));
                    }
                }
            }
        }
        TCGEN05_FENCE_BEFORE();
        __syncthreads();
    }
    __syncthreads();
    if (warp == 0) TCGEN05_DEALLOC(tmem, 512);
#else
    // ================= mma.sync fallback (compute_103 PTX pass; correctness only)
    const int PITCH = 80;
    int rowf = tid & 127, hlf = (tid >> 7) & 1;
    bool active = tid < 256;
    uint32_t stOff = (uint32_t)(rowf * PITCH + hlf * 32);
    int wm = (warp >> 2) & 1, wn = warp & 3;
    const int total = g_ntilel * (NDIM / 256) * NSPLIT;

    while (true) {
        if (tid == 0) {
            int w = atomicAdd(&g_work2[IS_UP ? 0 : 1], 1);
            *(int*)(smem + 32) = w;
        }
        __syncthreads();
        int w = *(int*)(smem + 32);
        __syncthreads();
        if (w >= total) break;
        int NTN2 = NDIM / 256;
        int n_i = w % NTN2;
        int t2 = w / NTN2;
        int kh = t2 % NSPLIT;
        int tl = g_tilelist[t2 / NSPLIT];
        int e = tl >> 8;
        int m0 = (tl & 255) * 256;
        int n0 = n_i * 256;
        int kbase = kh * KLEN;
        int cnt = g_fincnt[e];

#pragma unroll 1
        for (int mh = 0; mh < 2; mh++) {
            int m0h = m0 + mh * 128;
            const float* aSrcF = nullptr;
            const __half* aSrcH = nullptr;
            if (IS_UP) {
                int m = m0h + rowf;
                int mm = (m < cnt) ? m : 0;
                int tok = g_tokf[e * CAP + mm];
                aSrcF = xA + (size_t)tok * KDIM + kbase + hlf * 16;
            } else {
                aSrcH = g_h + ((size_t)e * CAP + m0h + rowf) * (size_t)KDIM + kbase + hlf * 16;
            }

#pragma unroll 1
            for (int hh2 = 0; hh2 < 2; hh2++) {
                int n0h = n0 + hh2 * 128;
                const float* bSrc = W + (size_t)e * NDIM * KDIM + (size_t)(n0h + rowf) * KDIM + kbase + hlf * 16;

                float acc[4][4][4];
#pragma unroll
                for (int i = 0; i < 4; i++)
#pragma unroll
                    for (int j = 0; j < 4; j++)
#pragma unroll
                        for (int q = 0; q < 4; q++) acc[i][j][q] = 0.f;

                const int KT = KLEN / 32;
#pragma unroll 1
                for (int kt = 0; kt < KT; kt++) {
                    int b = kt & 1;
                    char* Sp = smem + 1024 + b * 40960;
                    uint32_t S = sb + 1024 + b * 40960;
                    // load A (16 floats equivalent)
                    float4 va0, va1, va2, va3;
                    if (IS_UP) {
                        const float* a = aSrcF + kt * 32;
                        va0 = *(const float4*)(a + 0);  va1 = *(const float4*)(a + 4);
                        va2 = *(const float4*)(a + 8);  va3 = *(const float4*)(a + 12);
                    } else {
                        const __half* a = aSrcH + kt * 32;
                        float* v = (float*)&va0;
                        for (int q = 0; q < 16; q++) ((float*)&va0)[q] = __half2float(a[q]);
                        (void)v;
                    }
                    const float* bq0 = bSrc + kt * 32;
                    float4 vb0 = *(const float4*)(bq0 + 0), vb1 = *(const float4*)(bq0 + 4);
                    float4 vb2 = *(const float4*)(bq0 + 8), vb3 = *(const float4*)(bq0 + 12);
                    uint4 h0, l0, h1, l1;
                    hilo8(va0, va1, h0, l0); hilo8(va2, va3, h1, l1);
                    *(uint4*)(Sp + stOff) = h0;           *(uint4*)(Sp + stOff + 16) = h1;
                    *(uint4*)(Sp + 10240 + stOff) = l0;   *(uint4*)(Sp + 10240 + stOff + 16) = l1;
                    hilo8(vb0, vb1, h0, l0); hilo8(vb2, vb3, h1, l1);
                    *(uint4*)(Sp + 20480 + stOff) = h0;   *(uint4*)(Sp + 20480 + stOff + 16) = h1;
                    *(uint4*)(Sp + 30720 + stOff) = l0;   *(uint4*)(Sp + 30720 + stOff + 16) = l1;
                    __syncthreads();
                    if (active) {
#pragma unroll
                        for (int ks = 0; ks < 2; ks++) {
                            uint32_t kb = (uint32_t)(ks * 32);
                            uint32_t ah[4][4], al[4][4], bh[4][2], bl[4][2];
#pragma unroll
                            for (int i = 0; i < 4; i++) {
                                uint32_t ad = S + (uint32_t)((wm * 64 + i * 16 + (lane & 15)) * PITCH) + kb + ((lane >> 4) << 4);
                                LDSM4(ah[i][0], ah[i][1], ah[i][2], ah[i][3], ad);
                                LDSM4(al[i][0], al[i][1], al[i][2], al[i][3], ad + 10240);
                            }
#pragma unroll
                            for (int jp = 0; jp < 2; jp++) {
                                uint32_t bd = S + 20480
                                            + (uint32_t)((wn * 32 + jp * 16 + (lane & 7) + (((lane >> 4) & 1) << 3)) * PITCH)
                                            + kb + (((lane >> 3) & 1) << 4);
                                uint32_t q0, q1, q2, q3;
                                LDSM4(q0, q1, q2, q3, bd);
                                bh[2 * jp][0] = q0; bh[2 * jp][1] = q1;
                                bh[2 * jp + 1][0] = q2; bh[2 * jp + 1][1] = q3;
                                LDSM4(q0, q1, q2, q3, bd + 10240);
                                bl[2 * jp][0] = q0; bl[2 * jp][1] = q1;
                                bl[2 * jp + 1][0] = q2; bl[2 * jp + 1][1] = q3;
                            }
#pragma unroll
                            for (int i = 0; i < 4; i++)
#pragma unroll
                                for (int j = 0; j < 4; j++) {
                                    MMA_BF16(acc[i][j], ah[i], bh[j]);
                                    MMA_BF16(acc[i][j], ah[i], bl[j]);
                                    MMA_BF16(acc[i][j], al[i], bh[j]);
                                }
                        }
                    }
                    __syncthreads();
                }

                if (active) {
                    int g2 = lane >> 2, c2 = (lane & 3) * 2;
#pragma unroll
                    for (int i = 0; i < 4; i++) {
                        int rA = m0h + wm * 64 + i * 16 + g2;
                        int rB = rA + 8;
                        bool vA = rA < cnt, vB = rB < cnt;
                        if (IS_UP) {
                            __half* pA = g_h + ((size_t)e * CAP + rA) * (size_t)NDIM;
                            __half* pB = g_h + ((size_t)e * CAP + rB) * (size_t)NDIM;
#pragma unroll
                            for (int j = 0; j < 4; j++) {
                                int ccol = n0h + wn * 32 + j * 8 + c2;
                                float b0 = bias[(size_t)e * NDIM + ccol];
                                float b1 = bias[(size_t)e * NDIM + ccol + 1];
                                if (vA) {
                                    pA[ccol]     = __float2half(gelu_f(acc[i][j][0] + b0));
                                    pA[ccol + 1] = __float2half(gelu_f(acc[i][j][1] + b1));
                                }
                                if (vB) {
                                    pB[ccol]     = __float2half(gelu_f(acc[i][j][2] + b0));
                                    pB[ccol + 1] = __float2half(gelu_f(acc[i][j][3] + b1));
                                }
                            }
                        } else {
                            int tokA = 0, tokB = 0;
                            float wA = 0.f, wB = 0.f;
                            if (vA) { tokA = g_tokf[e * CAP + rA]; wA = g_wf[e * CAP + rA]; }
                            if (vB) { tokB = g_tokf[e * CAP + rB]; wB = g_wf[e * CAP + rB]; }
                            float* pA = outp + (size_t)tokA * HD;
                            float* pB = outp + (size_t)tokB * HD;
#pragma unroll
                            for (int j = 0; j < 4; j++) {
                                int ccol = n0h + wn * 32 + j * 8 + c2;
                                float b0 = (kh == 0) ? bias[(size_t)e * NDIM + ccol] : 0.f;
                                float b1 = (kh == 0) ? bias[(size_t)e * NDIM + ccol + 1] : 0.f;
                                if (vA) {
                                    atomicAdd(pA + ccol,     wA * (acc[i][j][0] + b0));
                                    atomicAdd(pA + ccol + 1, wA * (acc[i][j][1] + b1));
                                }
                                if (vB) {
                                    atomicAdd(pB + ccol,     wB * (acc[i][j][2] + b0));
                                    atomicAdd(pB + ccol + 1, wB * (acc[i][j][3] + b1));
                                }
                            }
                        }
                    }
                }
                __syncthreads();
            }
        }
    }
#endif
}

// ---------------- launch ----------------
extern "C" void kernel_launch(void* const* d_in, const int* in_sizes, int n_in,
                              void* d_out, int out_size) {
    const float* x   = (const float*)d_in[0];
    const float* Wr  = (const float*)d_in[1];
    const float* br  = (const float*)d_in[2];
    const float* Wup = (const float*)d_in[3];
    const float* bup = (const float*)d_in[4];
    const float* Wdn = (const float*)d_in[5];
    const float* bdn = (const float*)d_in[6];
    float* out = (float*)d_out;

    cudaFuncSetAttribute(k_moe_gemm<true, HD, FD, 1>, cudaFuncAttributeMaxDynamicSharedMemorySize, SMEM_GEMM);
    cudaFuncSetAttribute(k_moe_gemm<false, FD, HD, 4>, cudaFuncAttributeMaxDynamicSharedMemorySize, SMEM_GEMM);

    k_init<<<1, 32>>>();
    k_router<<<NTOK / 8, 256>>>(x, Wr, br, out);
    k_trim<<<NE, 256>>>(out, out_size);

    k_moe_gemm<true, HD, FD, 1><<<152, 512, SMEM_GEMM>>>(x, Wup, bup, nullptr);
    k_moe_gemm<false, FD, HD, 4><<<152, 512, SMEM_GEMM>>>(nullptr, Wdn, bdn, out);
}